// round 11
// baseline (speedup 1.0000x reference)
#include <cuda_runtime.h>

#define NN 100000
#define EE 1600000
#define HH 32
#define CC 10
#define GG 64
#define NBLK 98   // ceil(NN/1024)

typedef unsigned long long ull;

// ---------------- packed f32x2 helpers ----------------
__device__ __forceinline__ ull pack2(float lo, float hi) {
    ull r; asm("mov.b64 %0,{%1,%2};" : "=l"(r) : "f"(lo), "f"(hi)); return r;
}
__device__ __forceinline__ void unpack2(ull v, float& lo, float& hi) {
    asm("mov.b64 {%0,%1},%2;" : "=f"(lo), "=f"(hi) : "l"(v));
}
__device__ __forceinline__ ull fma2(ull a, ull b, ull c) {
    ull d; asm("fma.rn.f32x2 %0,%1,%2,%3;" : "=l"(d) : "l"(a), "l"(b), "l"(c)); return d;
}
__device__ __forceinline__ ull add2(ull a, ull b) {
    ull d; asm("add.rn.f32x2 %0,%1,%2;" : "=l"(d) : "l"(a), "l"(b)); return d;
}
__device__ __forceinline__ ull relu2(ull t) {
    float lo, hi; unpack2(t, lo, hi);
    lo = fmaxf(lo, 0.f); hi = fmaxf(hi, 0.f);
    return pack2(lo, hi);
}

// ---------------- scratch ----------------
__device__ int    d_cnt[NN];
__device__ int    d_cur[NN];
__device__ int    d_off[NN + 1];
__device__ int    d_rows[EE];
__device__ int    d_bsum[NBLK];
__device__ float  d_dinv[NN];
__device__ float4 d_xpad[NN];
__device__ float  d_xw1[NN * HH];
__device__ float  d_y[NN * HH];
__device__ float  d_h1[NN * HH];
__device__ float  d_xw2[NN * HH];
__device__ float  d_pooled[GG * HH];
__device__ ull    d_Ppk[5 * 3 * HH];
__device__ ull    d_Qpk[5 * 3 * HH];
__device__ ull    d_Cpk[5 * HH];
__device__ float  d_Gf[CC * HH * HH];   // [320][32]
__device__ float  d_biasE[HH];
__device__ float  d_Rs[NN * 320];       // 128MB scratch

// ---------------- setup: fold & pack weights + zero counters/pooled ----------------
__global__ void setup_k(const float* __restrict__ fW, const float* __restrict__ fb,
                        const float* __restrict__ W1, const float* __restrict__ b1,
                        const float* __restrict__ W2, const float* __restrict__ b2,
                        const float* __restrict__ g1W) {
    int stride = blockDim.x * gridDim.x;
    int t0 = threadIdx.x + blockIdx.x * blockDim.x;
    for (int i = t0; i < NN; i += stride) { d_cnt[i] = 0; d_cur[i] = 0; }
    for (int i = t0; i < GG * HH; i += stride) d_pooled[i] = 0.f;
    for (int t = t0; t < 5 * 3 * HH; t += stride) {
        int p = t / 96; int i = (t / 32) % 3; int h = t & 31;
        int c0 = 2 * p, c1 = 2 * p + 1;
        float pa0 = 0.f, pa1 = 0.f, qa0 = 0.f, qa1 = 0.f;
        for (int j = 0; j < HH; j++) {
            float w0 = fW[(c0 * 3 + i) * HH + j];
            float w1 = fW[(c1 * 3 + i) * HH + j];
            float u1 = W1[j * HH + h];
            float u2 = W1[(HH + j) * HH + h];
            pa0 += w0 * u1; pa1 += w1 * u1;
            qa0 += w0 * u2; qa1 += w1 * u2;
        }
        d_Ppk[t] = pack2(pa0, pa1);
        d_Qpk[t] = pack2(qa0, qa1);
    }
    for (int t = t0; t < 5 * HH; t += stride) {
        int p = t / 32; int h = t & 31;
        int c0 = 2 * p, c1 = 2 * p + 1;
        float s0 = b1[h], s1 = b1[h];
        for (int j = 0; j < HH; j++) {
            float u = W1[j * HH + h] + W1[(HH + j) * HH + h];
            s0 += fb[c0 * HH + j] * u;
            s1 += fb[c1 * HH + j] * u;
        }
        d_Cpk[t] = pack2(s0, s1);
    }
    for (int t = t0; t < CC * HH * HH; t += stride) {
        int c = t / (HH * HH); int i = (t / HH) % HH; int j = t & 31;
        float s = 0.f;
        for (int k = 0; k < HH; k++) s += W2[i * HH + k] * g1W[(3 + HH * c + k) * HH + j];
        d_Gf[t] = s;
    }
    for (int t = t0; t < HH; t += stride) {
        float s = 0.f;
        for (int c = 0; c < CC; c++)
            for (int k = 0; k < HH; k++) s += b2[k] * g1W[(3 + HH * c + k) * HH + t];
        d_biasE[t] = s;
    }
}

// ---------------- CSR build ----------------
__global__ void hist_k(const int* __restrict__ col) {
    int e = threadIdx.x + blockIdx.x * blockDim.x;
    if (e < EE) atomicAdd(&d_cnt[col[e]], 1);
}

__global__ void scanA_k() {
    __shared__ int wsum[32];
    int i = blockIdx.x * 1024 + threadIdx.x;
    int lane = threadIdx.x & 31, w = threadIdx.x >> 5;
    int v = (i < NN) ? d_cnt[i] : 0;
    #pragma unroll
    for (int d = 16; d > 0; d >>= 1) v += __shfl_down_sync(0xffffffffu, v, d);
    if (lane == 0) wsum[w] = v;
    __syncthreads();
    if (w == 0) {
        int s = wsum[lane];
        #pragma unroll
        for (int d = 16; d > 0; d >>= 1) s += __shfl_down_sync(0xffffffffu, s, d);
        if (lane == 0) d_bsum[blockIdx.x] = s;
    }
}
// scanC: per-block prefix of d_bsum computed in-kernel (scanB eliminated)
__global__ void scanC_k() {
    __shared__ int wsum[32];
    __shared__ int bpre_sh;
    int lane = threadIdx.x & 31, w = threadIdx.x >> 5;
    if (w == 0) {
        int ssum = 0;
        for (int i = lane; i < blockIdx.x; i += 32) ssum += d_bsum[i];
        #pragma unroll
        for (int d = 16; d > 0; d >>= 1) ssum += __shfl_down_sync(0xffffffffu, ssum, d);
        if (lane == 0) bpre_sh = ssum;
    }
    int i = blockIdx.x * 1024 + threadIdx.x;
    int v = (i < NN) ? d_cnt[i] : 0;
    int s = v;
    #pragma unroll
    for (int d = 1; d < 32; d <<= 1) {
        int u = __shfl_up_sync(0xffffffffu, s, d);
        if (lane >= d) s += u;
    }
    if (lane == 31) wsum[w] = s;
    __syncthreads();
    if (w == 0) {
        int t2 = wsum[lane];
        #pragma unroll
        for (int d = 1; d < 32; d <<= 1) {
            int u = __shfl_up_sync(0xffffffffu, t2, d);
            if (lane >= d) t2 += u;
        }
        wsum[lane] = t2;
    }
    __syncthreads();
    int base = bpre_sh + (w > 0 ? wsum[w - 1] : 0);
    if (i < NN) {
        d_off[i] = base + s - v;
        d_dinv[i] = rsqrtf((float)(v + 1));
    }
    if (i == NN - 1) d_off[NN] = base + s;
}

__global__ void fill_k(const int* __restrict__ row, const int* __restrict__ col) {
    int e = threadIdx.x + blockIdx.x * blockDim.x;
    if (e >= EE) return;
    int cn = col[e];
    int pos = atomicAdd(&d_cur[cn], 1);
    d_rows[d_off[cn] + pos] = row[e];
}

// ---------------- init: xpad + xw1 base ----------------
__global__ void init_k(const float* __restrict__ x, const float* __restrict__ g1W) {
    int t = threadIdx.x + blockIdx.x * blockDim.x;
    if (t >= NN * HH) return;
    int n = t >> 5; int h = t & 31;
    float x0 = x[n * 3 + 0], x1 = x[n * 3 + 1], x2 = x[n * 3 + 2];
    float indeg = (float)(d_off[n + 1] - d_off[n]);
    d_xw1[t] = x0 * g1W[h] + x1 * g1W[HH + h] + x2 * g1W[2 * HH + h] + indeg * d_biasE[h];
    if (h == 0) d_xpad[n] = make_float4(x0, x1, x2, 0.f);
}

// ---------------- fused 10-class edge MLP aggregation (monolithic, grid-stride) ----------------
__global__ void __launch_bounds__(256) edge_k() {
    __shared__ ull Qs[5 * 3 * HH];
    __shared__ ull Cs[5 * HH];
    for (int t = threadIdx.x; t < 5 * 3 * HH; t += blockDim.x) Qs[t] = d_Qpk[t];
    for (int t = threadIdx.x; t < 5 * HH; t += blockDim.x) Cs[t] = d_Cpk[t];
    __syncthreads();

    int lane = threadIdx.x & 31;
    int gw = (blockIdx.x * blockDim.x + threadIdx.x) >> 5;
    int nw = (gridDim.x * blockDim.x) >> 5;

    ull P0[5], P1[5], P2[5];
    #pragma unroll
    for (int p = 0; p < 5; p++) {
        P0[p] = d_Ppk[(p * 3 + 0) * HH + lane];
        P1[p] = d_Ppk[(p * 3 + 1) * HH + lane];
        P2[p] = d_Ppk[(p * 3 + 2) * HH + lane];
    }

    for (int n = gw; n < NN; n += nw) {
        float4 xn = d_xpad[n];
        ull xn0 = pack2(xn.x, xn.x), xn1 = pack2(xn.y, xn.y), xn2 = pack2(xn.z, xn.z);
        ull B[5], acc[5];
        #pragma unroll
        for (int p = 0; p < 5; p++) {
            ull b = fma2(xn0, Qs[(p * 3 + 0) * HH + lane], Cs[p * HH + lane]);
            b = fma2(xn1, Qs[(p * 3 + 1) * HH + lane], b);
            b = fma2(xn2, Qs[(p * 3 + 2) * HH + lane], b);
            B[p] = b;
            acc[p] = 0;
        }
        int k = d_off[n], ke = d_off[n + 1];
        for (; k + 2 <= ke; k += 2) {
            int r0 = __ldg(&d_rows[k]);
            int r1 = __ldg(&d_rows[k + 1]);
            float4 a = d_xpad[r0];
            float4 b4 = d_xpad[r1];
            ull a0 = pack2(a.x, a.x), a1 = pack2(a.y, a.y), a2 = pack2(a.z, a.z);
            ull c0 = pack2(b4.x, b4.x), c1 = pack2(b4.y, b4.y), c2 = pack2(b4.z, b4.z);
            #pragma unroll
            for (int p = 0; p < 5; p++) {
                ull t = fma2(a0, P0[p], B[p]);
                t = fma2(a1, P1[p], t);
                t = fma2(a2, P2[p], t);
                acc[p] = add2(acc[p], relu2(t));
                ull u = fma2(c0, P0[p], B[p]);
                u = fma2(c1, P1[p], u);
                u = fma2(c2, P2[p], u);
                acc[p] = add2(acc[p], relu2(u));
            }
        }
        if (k < ke) {
            int r0 = __ldg(&d_rows[k]);
            float4 a = d_xpad[r0];
            ull a0 = pack2(a.x, a.x), a1 = pack2(a.y, a.y), a2 = pack2(a.z, a.z);
            #pragma unroll
            for (int p = 0; p < 5; p++) {
                ull t = fma2(a0, P0[p], B[p]);
                t = fma2(a1, P1[p], t);
                t = fma2(a2, P2[p], t);
                acc[p] = add2(acc[p], relu2(t));
            }
        }
        float* rs = d_Rs + n * 320;
        #pragma unroll
        for (int p = 0; p < 5; p++) {
            float lo, hi; unpack2(acc[p], lo, hi);
            rs[(2 * p) * HH + lane] = lo;
            rs[(2 * p + 1) * HH + lane] = hi;
        }
    }
}

// ---------------- tiled GEMM (8x8 per thread, conflict-free): xw1 += Rs@Gf; y = xw1*dinv ----
// 128 threads, 256 rows/block. Warp lane: rs = l&7 (row-sub), tx = l>>3 (j-group of 8).
// Thread rows: w*64 + rs + m*8 (m=0..7) -> per-LDS32 the 8 lane-rows differ by 1 (stride-33
// banks all distinct). Thread cols: tx*8..tx*8+7.
#define KC 32
__global__ void __launch_bounds__(128) gemm_k() {
    __shared__ float As[256][KC + 1];   // stride 33: conflict-free for row-diff-1 access
    __shared__ float Gsh[KC][HH];
    int t = threadIdx.x;
    int w = t >> 5, l = t & 31;
    int rs = l & 7, tx = l >> 3;
    int rowb = w * 64 + rs;             // + m*8
    int n0 = blockIdx.x * 256;
    ull acc[8][4];
    #pragma unroll
    for (int m = 0; m < 8; m++)
        #pragma unroll
        for (int j = 0; j < 4; j++) acc[m][j] = 0;

    for (int kc = 0; kc < 320; kc += KC) {
        __syncthreads();
        // load As: 256 rows x 32 cols; thread-linear i -> (row = i>>5, kk = i&31): coalesced
        for (int i = t; i < 256 * KC; i += 128) {
            int r = i >> 5, kk = i & 31;
            int n = n0 + r;
            As[r][kk] = (n < NN) ? d_Rs[n * 320 + kc + kk] : 0.f;
        }
        for (int i = t; i < KC * HH; i += 128)
            Gsh[i >> 5][i & 31] = d_Gf[(kc + (i >> 5)) * HH + (i & 31)];
        __syncthreads();
        #pragma unroll 4
        for (int kk = 0; kk < KC; kk++) {
            float4 ga = *(const float4*)&Gsh[kk][tx * 8];
            float4 gb = *(const float4*)&Gsh[kk][tx * 8 + 4];
            ull g0 = pack2(ga.x, ga.y), g1 = pack2(ga.z, ga.w);
            ull g2 = pack2(gb.x, gb.y), g3 = pack2(gb.z, gb.w);
            #pragma unroll
            for (int m = 0; m < 8; m++) {
                float a = As[rowb + m * 8][kk];
                ull ap = pack2(a, a);
                acc[m][0] = fma2(ap, g0, acc[m][0]);
                acc[m][1] = fma2(ap, g1, acc[m][1]);
                acc[m][2] = fma2(ap, g2, acc[m][2]);
                acc[m][3] = fma2(ap, g3, acc[m][3]);
            }
        }
    }
    #pragma unroll
    for (int m = 0; m < 8; m++) {
        int n = n0 + rowb + m * 8;
        if (n < NN) {
            float o[8];
            unpack2(acc[m][0], o[0], o[1]);
            unpack2(acc[m][1], o[2], o[3]);
            unpack2(acc[m][2], o[4], o[5]);
            unpack2(acc[m][3], o[6], o[7]);
            float4 c0 = *(const float4*)&d_xw1[n * HH + tx * 8];
            float4 c1 = *(const float4*)&d_xw1[n * HH + tx * 8 + 4];
            o[0] += c0.x; o[1] += c0.y; o[2] += c0.z; o[3] += c0.w;
            o[4] += c1.x; o[5] += c1.y; o[6] += c1.z; o[7] += c1.w;
            *(float4*)&d_xw1[n * HH + tx * 8]     = make_float4(o[0], o[1], o[2], o[3]);
            *(float4*)&d_xw1[n * HH + tx * 8 + 4] = make_float4(o[4], o[5], o[6], o[7]);
            float dv = d_dinv[n];
            *(float4*)&d_y[n * HH + tx * 8]     = make_float4(o[0]*dv, o[1]*dv, o[2]*dv, o[3]*dv);
            *(float4*)&d_y[n * HH + tx * 8 + 4] = make_float4(o[4]*dv, o[5]*dv, o[6]*dv, o[7]*dv);
        }
    }
}

// ---------------- GCN layer 1 gather ----------------
__global__ void gcn1_k(const float* __restrict__ g1b) {
    int lane = threadIdx.x & 31;
    int n = blockIdx.x * (blockDim.x >> 5) + (threadIdx.x >> 5);
    if (n >= NN) return;
    int base = d_off[n], end = d_off[n + 1];
    float a0 = 0.f, a1 = 0.f, a2 = 0.f, a3 = 0.f;
    int k = base;
    for (; k + 4 <= end; k += 4) {
        int r0 = __ldg(&d_rows[k + 0]), r1 = __ldg(&d_rows[k + 1]);
        int r2 = __ldg(&d_rows[k + 2]), r3 = __ldg(&d_rows[k + 3]);
        a0 += d_y[r0 * HH + lane]; a1 += d_y[r1 * HH + lane];
        a2 += d_y[r2 * HH + lane]; a3 += d_y[r3 * HH + lane];
    }
    for (; k < end; k++) a0 += d_y[__ldg(&d_rows[k]) * HH + lane];
    float acc = (a0 + a1) + (a2 + a3);
    float dv = d_dinv[n];
    float v = dv * acc + dv * dv * d_xw1[n * HH + lane] + g1b[lane];
    d_h1[n * HH + lane] = fmaxf(v, 0.f);
}

// ---------------- xw2 = h1 @ gcn2_W; y = xw2*dinv ----------------
__global__ void xw2_k(const float* __restrict__ g2W) {
    __shared__ float Ws[HH * HH];
    for (int t = threadIdx.x; t < HH * HH; t += blockDim.x) Ws[t] = g2W[t];
    __syncthreads();
    int t = threadIdx.x + blockIdx.x * blockDim.x;
    if (t >= NN * HH) return;
    int n = t >> 5; int j = t & 31;
    const float* h = d_h1 + n * HH;
    float s = 0.f;
    #pragma unroll
    for (int kk = 0; kk < HH; kk++) s += h[kk] * Ws[kk * HH + j];
    d_xw2[t] = s;
    d_y[t] = s * d_dinv[n];
}

// ---------------- GCN layer 2 gather + pooling ----------------
__global__ void gcn2p_k(const float* __restrict__ g2b, const int* __restrict__ batch) {
    int lane = threadIdx.x & 31;
    int n = blockIdx.x * (blockDim.x >> 5) + (threadIdx.x >> 5);
    if (n >= NN) return;
    int base = d_off[n], end = d_off[n + 1];
    float a0 = 0.f, a1 = 0.f, a2 = 0.f, a3 = 0.f;
    int k = base;
    for (; k + 4 <= end; k += 4) {
        int r0 = __ldg(&d_rows[k + 0]), r1 = __ldg(&d_rows[k + 1]);
        int r2 = __ldg(&d_rows[k + 2]), r3 = __ldg(&d_rows[k + 3]);
        a0 += d_y[r0 * HH + lane]; a1 += d_y[r1 * HH + lane];
        a2 += d_y[r2 * HH + lane]; a3 += d_y[r3 * HH + lane];
    }
    for (; k < end; k++) a0 += d_y[__ldg(&d_rows[k]) * HH + lane];
    float acc = (a0 + a1) + (a2 + a3);
    float dv = d_dinv[n];
    float v = fmaxf(dv * acc + dv * dv * d_xw2[n * HH + lane] + g2b[lane], 0.f);
    atomicAdd(&d_pooled[batch[n] * HH + lane], v);
}

// ---------------- classifier (graph sizes via binary search on sorted batch) ----------------
__global__ void cls_k(const int* __restrict__ batch,
                      const float* __restrict__ clsW, const float* __restrict__ clsb,
                      float* __restrict__ out) {
    int t = threadIdx.x + blockIdx.x * blockDim.x;
    if (t >= GG * CC) return;
    int g = t / CC; int j = t % CC;
    int lo = 0, hi = NN;
    while (lo < hi) { int m = (lo + hi) >> 1; if (batch[m] < g) lo = m + 1; else hi = m; }
    int s0 = lo;
    hi = NN;
    while (lo < hi) { int m = (lo + hi) >> 1; if (batch[m] < g + 1) lo = m + 1; else hi = m; }
    float cnt = fmaxf((float)(lo - s0), 1.0f);
    float inv = 1.0f / cnt;
    float s = clsb[j];
    #pragma unroll
    for (int k = 0; k < HH; k++) s += d_pooled[g * HH + k] * inv * clsW[k * CC + j];
    out[t] = s;
}

// ---------------- launch ----------------
extern "C" void kernel_launch(void* const* d_in, const int* in_sizes, int n_in,
                              void* d_out, int out_size) {
    const float* x     = (const float*)d_in[0];
    const int*   ei    = (const int*)d_in[1];
    const int*   row   = ei;
    const int*   col   = ei + EE;
    const int*   batch = (const int*)d_in[2];
    const float* fW    = (const float*)d_in[3];
    const float* fb    = (const float*)d_in[4];
    const float* W1    = (const float*)d_in[5];
    const float* b1    = (const float*)d_in[6];
    const float* W2    = (const float*)d_in[7];
    const float* b2    = (const float*)d_in[8];
    const float* g1W   = (const float*)d_in[9];
    const float* g1b   = (const float*)d_in[10];
    const float* g2W   = (const float*)d_in[11];
    const float* g2b   = (const float*)d_in[12];
    const float* clsW  = (const float*)d_in[13];
    const float* clsb  = (const float*)d_in[14];
    float* out = (float*)d_out;

    const int TB = 256;
    const int gridE  = (EE + TB - 1) / TB;          // 6250
    const int gridN  = (NN + TB - 1) / TB;          // 391
    const int gridNH = (NN * HH + TB - 1) / TB;     // 12500

    setup_k<<<128, TB>>>(fW, fb, W1, b1, W2, b2, g1W);
    hist_k<<<gridE, TB>>>(col);
    scanA_k<<<NBLK, 1024>>>();
    scanC_k<<<NBLK, 1024>>>();
    fill_k<<<gridE, TB>>>(row, col);
    init_k<<<gridNH, TB>>>(x, g1W);
    edge_k<<<1184, TB>>>();
    gemm_k<<<gridN, 128>>>();
    gcn1_k<<<gridNH, TB>>>(g1b);
    xw2_k<<<gridNH, TB>>>(g2W);
    gcn2p_k<<<gridNH, TB>>>(g2b, batch);
    cls_k<<<(GG * CC + TB - 1) / TB, TB>>>(batch, clsW, clsb, out);
}

// round 12
// speedup vs baseline: 1.2713x; 1.2713x over previous
#include <cuda_runtime.h>
#include <cuda_fp16.h>

#define NN 100000
#define EE 1600000
#define HH 32
#define CC 10
#define GG 64
#define NBLK 98   // ceil(NN/1024)

typedef unsigned long long ull;

// ---------------- packed f32x2 helpers ----------------
__device__ __forceinline__ ull pack2(float lo, float hi) {
    ull r; asm("mov.b64 %0,{%1,%2};" : "=l"(r) : "f"(lo), "f"(hi)); return r;
}
__device__ __forceinline__ void unpack2(ull v, float& lo, float& hi) {
    asm("mov.b64 {%0,%1},%2;" : "=f"(lo), "=f"(hi) : "l"(v));
}
__device__ __forceinline__ ull fma2(ull a, ull b, ull c) {
    ull d; asm("fma.rn.f32x2 %0,%1,%2,%3;" : "=l"(d) : "l"(a), "l"(b), "l"(c)); return d;
}
__device__ __forceinline__ ull add2(ull a, ull b) {
    ull d; asm("add.rn.f32x2 %0,%1,%2;" : "=l"(d) : "l"(a), "l"(b)); return d;
}
__device__ __forceinline__ ull relu2(ull t) {
    float lo, hi; unpack2(t, lo, hi);
    lo = fmaxf(lo, 0.f); hi = fmaxf(hi, 0.f);
    return pack2(lo, hi);
}

// ---------------- scratch ----------------
__device__ int     d_cnt[NN];
__device__ int     d_cur[NN];
__device__ int     d_off[NN + 1];
__device__ int     d_rows[EE];
__device__ int     d_bsum[NBLK];
__device__ int     d_gstart[GG + 1];
__device__ float   d_dinv[NN];
__device__ float4  d_xpad[NN];
__device__ float   d_xw1[NN * HH];
__device__ float   d_y[NN * HH];
__device__ float   d_h1[NN * HH];
__device__ float   d_xw2[NN * HH];
__device__ float   d_h2[NN * HH];
__device__ ull     d_Ppk[5 * 3 * HH];
__device__ ull     d_Qpk[5 * 3 * HH];
__device__ ull     d_Cpk[5 * HH];
__device__ float   d_Gf[CC * HH * HH];   // [320][32]
__device__ float   d_biasE[HH];
__device__ __half2 d_Rsh[NN * 160];      // 64MB — fits in 126MB L2: no DRAM round-trip

// ---------------- setup: fold & pack weights ----------------
__global__ void setup_k(const float* __restrict__ fW, const float* __restrict__ fb,
                        const float* __restrict__ W1, const float* __restrict__ b1,
                        const float* __restrict__ W2, const float* __restrict__ b2,
                        const float* __restrict__ g1W) {
    int stride = blockDim.x * gridDim.x;
    int t0 = threadIdx.x + blockIdx.x * blockDim.x;
    for (int t = t0; t < 5 * 3 * HH; t += stride) {
        int p = t / 96; int i = (t / 32) % 3; int h = t & 31;
        int c0 = 2 * p, c1 = 2 * p + 1;
        float pa0 = 0.f, pa1 = 0.f, qa0 = 0.f, qa1 = 0.f;
        for (int j = 0; j < HH; j++) {
            float w0 = fW[(c0 * 3 + i) * HH + j];
            float w1 = fW[(c1 * 3 + i) * HH + j];
            float u1 = W1[j * HH + h];
            float u2 = W1[(HH + j) * HH + h];
            pa0 += w0 * u1; pa1 += w1 * u1;
            qa0 += w0 * u2; qa1 += w1 * u2;
        }
        d_Ppk[t] = pack2(pa0, pa1);
        d_Qpk[t] = pack2(qa0, qa1);
    }
    for (int t = t0; t < 5 * HH; t += stride) {
        int p = t / 32; int h = t & 31;
        int c0 = 2 * p, c1 = 2 * p + 1;
        float s0 = b1[h], s1 = b1[h];
        for (int j = 0; j < HH; j++) {
            float u = W1[j * HH + h] + W1[(HH + j) * HH + h];
            s0 += fb[c0 * HH + j] * u;
            s1 += fb[c1 * HH + j] * u;
        }
        d_Cpk[t] = pack2(s0, s1);
    }
    for (int t = t0; t < CC * HH * HH; t += stride) {
        int c = t / (HH * HH); int i = (t / HH) % HH; int j = t & 31;
        float s = 0.f;
        for (int k = 0; k < HH; k++) s += W2[i * HH + k] * g1W[(3 + HH * c + k) * HH + j];
        d_Gf[t] = s;
    }
    for (int t = t0; t < HH; t += stride) {
        float s = 0.f;
        for (int c = 0; c < CC; c++)
            for (int k = 0; k < HH; k++) s += b2[k] * g1W[(3 + HH * c + k) * HH + t];
        d_biasE[t] = s;
    }
}

// ---------------- zeroing ----------------
__global__ void zero_k() {
    int t = threadIdx.x + blockIdx.x * blockDim.x;
    int stride = blockDim.x * gridDim.x;
    for (int i = t; i < NN; i += stride) { d_cnt[i] = 0; d_cur[i] = 0; }
}

// ---------------- CSR build ----------------
__global__ void hist_k(const int* __restrict__ col) {
    int e = threadIdx.x + blockIdx.x * blockDim.x;
    if (e < EE) atomicAdd(&d_cnt[col[e]], 1);
}

__global__ void gstart_k(const int* __restrict__ batch) {
    int n = threadIdx.x + blockIdx.x * blockDim.x;
    if (n >= NN) return;
    int g = batch[n];
    int gp = n ? batch[n - 1] : -1;
    if (g != gp) for (int q = gp + 1; q <= g; q++) d_gstart[q] = n;
    if (n == NN - 1) for (int q = g + 1; q <= GG; q++) d_gstart[q] = NN;
}

__global__ void scanA_k() {
    __shared__ int wsum[32];
    int i = blockIdx.x * 1024 + threadIdx.x;
    int lane = threadIdx.x & 31, w = threadIdx.x >> 5;
    int v = (i < NN) ? d_cnt[i] : 0;
    #pragma unroll
    for (int d = 16; d > 0; d >>= 1) v += __shfl_down_sync(0xffffffffu, v, d);
    if (lane == 0) wsum[w] = v;
    __syncthreads();
    if (w == 0) {
        int s = wsum[lane];
        #pragma unroll
        for (int d = 16; d > 0; d >>= 1) s += __shfl_down_sync(0xffffffffu, s, d);
        if (lane == 0) d_bsum[blockIdx.x] = s;
    }
}
__global__ void scanB_k() {
    int lane = threadIdx.x;
    int carry = 0;
    for (int base = 0; base < NBLK; base += 32) {
        int i = base + lane;
        int v = (i < NBLK) ? d_bsum[i] : 0;
        int s = v;
        #pragma unroll
        for (int d = 1; d < 32; d <<= 1) {
            int u = __shfl_up_sync(0xffffffffu, s, d);
            if (lane >= d) s += u;
        }
        if (i < NBLK) d_bsum[i] = carry + s - v;
        carry += __shfl_sync(0xffffffffu, s, 31);
    }
}
__global__ void scanC_k() {
    __shared__ int wsum[32];
    int i = blockIdx.x * 1024 + threadIdx.x;
    int lane = threadIdx.x & 31, w = threadIdx.x >> 5;
    int v = (i < NN) ? d_cnt[i] : 0;
    int s = v;
    #pragma unroll
    for (int d = 1; d < 32; d <<= 1) {
        int u = __shfl_up_sync(0xffffffffu, s, d);
        if (lane >= d) s += u;
    }
    if (lane == 31) wsum[w] = s;
    __syncthreads();
    if (w == 0) {
        int t2 = wsum[lane];
        #pragma unroll
        for (int d = 1; d < 32; d <<= 1) {
            int u = __shfl_up_sync(0xffffffffu, t2, d);
            if (lane >= d) t2 += u;
        }
        wsum[lane] = t2;
    }
    __syncthreads();
    int base = d_bsum[blockIdx.x] + (w > 0 ? wsum[w - 1] : 0);
    if (i < NN) {
        d_off[i] = base + s - v;
        d_dinv[i] = rsqrtf((float)(v + 1));
    }
    if (i == NN - 1) d_off[NN] = base + s;
}

__global__ void fill_k(const int* __restrict__ row, const int* __restrict__ col) {
    int e = threadIdx.x + blockIdx.x * blockDim.x;
    if (e >= EE) return;
    int cn = col[e];
    int pos = atomicAdd(&d_cur[cn], 1);
    d_rows[d_off[cn] + pos] = row[e];
}

// ---------------- init: xpad + xw1 base ----------------
__global__ void init_k(const float* __restrict__ x, const float* __restrict__ g1W) {
    int t = threadIdx.x + blockIdx.x * blockDim.x;
    if (t >= NN * HH) return;
    int n = t >> 5; int h = t & 31;
    float x0 = x[n * 3 + 0], x1 = x[n * 3 + 1], x2 = x[n * 3 + 2];
    float indeg = (float)(d_off[n + 1] - d_off[n]);
    d_xw1[t] = x0 * g1W[h] + x1 * g1W[HH + h] + x2 * g1W[2 * HH + h] + indeg * d_biasE[h];
    if (h == 0) d_xpad[n] = make_float4(x0, x1, x2, 0.f);
}

// ---------------- fused 10-class edge MLP aggregation (monolithic, grid-stride) ----------------
__global__ void __launch_bounds__(256) edge_k() {
    __shared__ ull Qs[5 * 3 * HH];
    __shared__ ull Cs[5 * HH];
    for (int t = threadIdx.x; t < 5 * 3 * HH; t += blockDim.x) Qs[t] = d_Qpk[t];
    for (int t = threadIdx.x; t < 5 * HH; t += blockDim.x) Cs[t] = d_Cpk[t];
    __syncthreads();

    int lane = threadIdx.x & 31;
    int gw = (blockIdx.x * blockDim.x + threadIdx.x) >> 5;
    int nw = (gridDim.x * blockDim.x) >> 5;

    ull P0[5], P1[5], P2[5];
    #pragma unroll
    for (int p = 0; p < 5; p++) {
        P0[p] = d_Ppk[(p * 3 + 0) * HH + lane];
        P1[p] = d_Ppk[(p * 3 + 1) * HH + lane];
        P2[p] = d_Ppk[(p * 3 + 2) * HH + lane];
    }

    for (int n = gw; n < NN; n += nw) {
        float4 xn = d_xpad[n];
        ull xn0 = pack2(xn.x, xn.x), xn1 = pack2(xn.y, xn.y), xn2 = pack2(xn.z, xn.z);
        ull B[5], acc[5];
        #pragma unroll
        for (int p = 0; p < 5; p++) {
            ull b = fma2(xn0, Qs[(p * 3 + 0) * HH + lane], Cs[p * HH + lane]);
            b = fma2(xn1, Qs[(p * 3 + 1) * HH + lane], b);
            b = fma2(xn2, Qs[(p * 3 + 2) * HH + lane], b);
            B[p] = b;
            acc[p] = 0;
        }
        int k = d_off[n], ke = d_off[n + 1];
        for (; k + 2 <= ke; k += 2) {
            int r0 = __ldg(&d_rows[k]);
            int r1 = __ldg(&d_rows[k + 1]);
            float4 a = d_xpad[r0];
            float4 b4 = d_xpad[r1];
            ull a0 = pack2(a.x, a.x), a1 = pack2(a.y, a.y), a2 = pack2(a.z, a.z);
            ull c0 = pack2(b4.x, b4.x), c1 = pack2(b4.y, b4.y), c2 = pack2(b4.z, b4.z);
            #pragma unroll
            for (int p = 0; p < 5; p++) {
                ull t = fma2(a0, P0[p], B[p]);
                t = fma2(a1, P1[p], t);
                t = fma2(a2, P2[p], t);
                acc[p] = add2(acc[p], relu2(t));
                ull u = fma2(c0, P0[p], B[p]);
                u = fma2(c1, P1[p], u);
                u = fma2(c2, P2[p], u);
                acc[p] = add2(acc[p], relu2(u));
            }
        }
        if (k < ke) {
            int r0 = __ldg(&d_rows[k]);
            float4 a = d_xpad[r0];
            ull a0 = pack2(a.x, a.x), a1 = pack2(a.y, a.y), a2 = pack2(a.z, a.z);
            #pragma unroll
            for (int p = 0; p < 5; p++) {
                ull t = fma2(a0, P0[p], B[p]);
                t = fma2(a1, P1[p], t);
                t = fma2(a2, P2[p], t);
                acc[p] = add2(acc[p], relu2(t));
            }
        }
        // store fp16: H[n*160 + p*32 + lane] = (col 64p+lane, col 64p+32+lane)
        __half2* rs = d_Rsh + n * 160;
        #pragma unroll
        for (int p = 0; p < 5; p++) {
            float lo, hi; unpack2(acc[p], lo, hi);
            rs[p * HH + lane] = __floats2half2_rn(lo, hi);
        }
    }
}

// ---------------- tiled GEMM: xw1 += Rs[N,320] @ Gf[320,32]; y = xw1*dinv ----------------
// fp16 Rs, 64-column chunks (one class-pair group pc per chunk; As col kk = global col 64pc+kk).
// 256 threads, 128 rows/block. tx=t&7 -> cols tx*4..+3, ty=t>>3 -> rows ty*4..+3.
__global__ void __launch_bounds__(256) gemm_k() {
    __shared__ float As[128][65];    // 33.3KB; row-diff 4 -> bank-diff 4: conflict-free
    __shared__ float Gsh[64][HH];    // 8KB
    int t = threadIdx.x;
    int warp = t >> 5, lane = t & 31;
    int tx = t & 7, ty = t >> 3;
    int n0 = blockIdx.x * 128;
    ull acc[4][2];
    #pragma unroll
    for (int m = 0; m < 4; m++) { acc[m][0] = 0; acc[m][1] = 0; }

    for (int pc = 0; pc < 5; pc++) {
        __syncthreads();
        for (int i = t; i < 64 * HH; i += 256)
            Gsh[i >> 5][i & 31] = d_Gf[(pc * 64 + (i >> 5)) * HH + (i & 31)];
        #pragma unroll 4
        for (int it = 0; it < 16; it++) {
            int r = warp * 16 + it;
            int n = n0 + r;
            __half2 h = (n < NN) ? d_Rsh[n * 160 + pc * 32 + lane]
                                 : __floats2half2_rn(0.f, 0.f);
            As[r][lane] = __low2float(h);
            As[r][32 + lane] = __high2float(h);
        }
        __syncthreads();
        #pragma unroll 8
        for (int kk = 0; kk < 64; kk++) {
            float4 g4 = *(const float4*)&Gsh[kk][tx * 4];
            ull g0 = pack2(g4.x, g4.y), g1 = pack2(g4.z, g4.w);
            #pragma unroll
            for (int m = 0; m < 4; m++) {
                float a = As[ty * 4 + m][kk];
                ull ap = pack2(a, a);
                acc[m][0] = fma2(ap, g0, acc[m][0]);
                acc[m][1] = fma2(ap, g1, acc[m][1]);
            }
        }
    }
    #pragma unroll
    for (int m = 0; m < 4; m++) {
        int n = n0 + ty * 4 + m;
        if (n < NN) {
            float o0, o1, o2, o3;
            unpack2(acc[m][0], o0, o1);
            unpack2(acc[m][1], o2, o3);
            float4 cur = *(const float4*)&d_xw1[n * HH + tx * 4];
            o0 += cur.x; o1 += cur.y; o2 += cur.z; o3 += cur.w;
            *(float4*)&d_xw1[n * HH + tx * 4] = make_float4(o0, o1, o2, o3);
            float dv = d_dinv[n];
            *(float4*)&d_y[n * HH + tx * 4] = make_float4(o0 * dv, o1 * dv, o2 * dv, o3 * dv);
        }
    }
}

// ---------------- GCN layer 1 gather ----------------
__global__ void gcn1_k(const float* __restrict__ g1b) {
    int lane = threadIdx.x & 31;
    int n = blockIdx.x * (blockDim.x >> 5) + (threadIdx.x >> 5);
    if (n >= NN) return;
    int base = d_off[n], end = d_off[n + 1];
    float a0 = 0.f, a1 = 0.f, a2 = 0.f, a3 = 0.f;
    int k = base;
    for (; k + 4 <= end; k += 4) {
        int r0 = __ldg(&d_rows[k + 0]), r1 = __ldg(&d_rows[k + 1]);
        int r2 = __ldg(&d_rows[k + 2]), r3 = __ldg(&d_rows[k + 3]);
        a0 += d_y[r0 * HH + lane]; a1 += d_y[r1 * HH + lane];
        a2 += d_y[r2 * HH + lane]; a3 += d_y[r3 * HH + lane];
    }
    for (; k < end; k++) a0 += d_y[__ldg(&d_rows[k]) * HH + lane];
    float acc = (a0 + a1) + (a2 + a3);
    float dv = d_dinv[n];
    float v = dv * acc + dv * dv * d_xw1[n * HH + lane] + g1b[lane];
    d_h1[n * HH + lane] = fmaxf(v, 0.f);
}

// ---------------- xw2 = h1 @ gcn2_W; y = xw2*dinv ----------------
__global__ void xw2_k(const float* __restrict__ g2W) {
    __shared__ float Ws[HH * HH];
    for (int t = threadIdx.x; t < HH * HH; t += blockDim.x) Ws[t] = g2W[t];
    __syncthreads();
    int t = threadIdx.x + blockIdx.x * blockDim.x;
    if (t >= NN * HH) return;
    int n = t >> 5; int j = t & 31;
    const float* h = d_h1 + n * HH;
    float s = 0.f;
    #pragma unroll
    for (int kk = 0; kk < HH; kk++) s += h[kk] * Ws[kk * HH + j];
    d_xw2[t] = s;
    d_y[t] = s * d_dinv[n];
}

// ---------------- GCN layer 2 gather -> h2 ----------------
__global__ void gcn2_k(const float* __restrict__ g2b) {
    int lane = threadIdx.x & 31;
    int n = blockIdx.x * (blockDim.x >> 5) + (threadIdx.x >> 5);
    if (n >= NN) return;
    int base = d_off[n], end = d_off[n + 1];
    float a0 = 0.f, a1 = 0.f, a2 = 0.f, a3 = 0.f;
    int k = base;
    for (; k + 4 <= end; k += 4) {
        int r0 = __ldg(&d_rows[k + 0]), r1 = __ldg(&d_rows[k + 1]);
        int r2 = __ldg(&d_rows[k + 2]), r3 = __ldg(&d_rows[k + 3]);
        a0 += d_y[r0 * HH + lane]; a1 += d_y[r1 * HH + lane];
        a2 += d_y[r2 * HH + lane]; a3 += d_y[r3 * HH + lane];
    }
    for (; k < end; k++) a0 += d_y[__ldg(&d_rows[k]) * HH + lane];
    float acc = (a0 + a1) + (a2 + a3);
    float dv = d_dinv[n];
    float v = dv * acc + dv * dv * d_xw2[n * HH + lane] + g2b[lane];
    d_h2[n * HH + lane] = fmaxf(v, 0.f);
}

// ---------------- mean pool (per graph, no atomics) + classifier ----------------
__global__ void pool_cls_k(const float* __restrict__ clsW, const float* __restrict__ clsb,
                           float* __restrict__ out) {
    __shared__ float red[8][HH];
    __shared__ float pooled[HH];
    int g = blockIdx.x;
    int lane = threadIdx.x & 31, w = threadIdx.x >> 5;
    int s = d_gstart[g], e = d_gstart[g + 1];
    float acc = 0.f;
    for (int n = s + w; n < e; n += 8) acc += d_h2[n * HH + lane];
    red[w][lane] = acc;
    __syncthreads();
    if (w == 0) {
        float v = red[0][lane];
        #pragma unroll
        for (int i = 1; i < 8; i++) v += red[i][lane];
        float cnt = fmaxf((float)(e - s), 1.f);
        pooled[lane] = v / cnt;
    }
    __syncthreads();
    if (threadIdx.x < CC) {
        float sres = clsb[threadIdx.x];
        #pragma unroll
        for (int k2 = 0; k2 < HH; k2++) sres += pooled[k2] * clsW[k2 * CC + threadIdx.x];
        out[g * CC + threadIdx.x] = sres;
    }
}

// ---------------- launch ----------------
extern "C" void kernel_launch(void* const* d_in, const int* in_sizes, int n_in,
                              void* d_out, int out_size) {
    const float* x     = (const float*)d_in[0];
    const int*   ei    = (const int*)d_in[1];
    const int*   row   = ei;
    const int*   col   = ei + EE;
    const int*   batch = (const int*)d_in[2];
    const float* fW    = (const float*)d_in[3];
    const float* fb    = (const float*)d_in[4];
    const float* W1    = (const float*)d_in[5];
    const float* b1    = (const float*)d_in[6];
    const float* W2    = (const float*)d_in[7];
    const float* b2    = (const float*)d_in[8];
    const float* g1W   = (const float*)d_in[9];
    const float* g1b   = (const float*)d_in[10];
    const float* g2W   = (const float*)d_in[11];
    const float* g2b   = (const float*)d_in[12];
    const float* clsW  = (const float*)d_in[13];
    const float* clsb  = (const float*)d_in[14];
    float* out = (float*)d_out;

    const int TB = 256;
    const int gridE  = (EE + TB - 1) / TB;          // 6250
    const int gridN128 = (NN + 127) / 128;          // 782
    const int gridN  = (NN + TB - 1) / TB;          // 391
    const int gridNH = (NN * HH + TB - 1) / TB;     // 12500

    setup_k<<<64, TB>>>(fW, fb, W1, b1, W2, b2, g1W);
    zero_k<<<128, TB>>>();
    hist_k<<<gridE, TB>>>(col);
    gstart_k<<<gridN, TB>>>(batch);
    scanA_k<<<NBLK, 1024>>>();
    scanB_k<<<1, 32>>>();
    scanC_k<<<NBLK, 1024>>>();
    fill_k<<<gridE, TB>>>(row, col);
    init_k<<<gridNH, TB>>>(x, g1W);
    edge_k<<<1184, TB>>>();
    gemm_k<<<gridN128, TB>>>();
    gcn1_k<<<gridNH, TB>>>(g1b);
    xw2_k<<<gridNH, TB>>>(g2W);
    gcn2_k<<<gridNH, TB>>>(g2b);
    pool_cls_k<<<GG, TB>>>(clsW, clsb, out);
}

// round 13
// speedup vs baseline: 1.3479x; 1.0602x over previous
#include <cuda_runtime.h>
#include <cuda_fp16.h>

#define NN 100000
#define EE 1600000
#define HH 32
#define CC 10
#define GG 64
#define NBLK 98   // ceil(NN/1024)

typedef unsigned long long ull;

// ---------------- packed f32x2 helpers ----------------
__device__ __forceinline__ ull pack2(float lo, float hi) {
    ull r; asm("mov.b64 %0,{%1,%2};" : "=l"(r) : "f"(lo), "f"(hi)); return r;
}
__device__ __forceinline__ void unpack2(ull v, float& lo, float& hi) {
    asm("mov.b64 {%0,%1},%2;" : "=f"(lo), "=f"(hi) : "l"(v));
}
__device__ __forceinline__ ull fma2(ull a, ull b, ull c) {
    ull d; asm("fma.rn.f32x2 %0,%1,%2,%3;" : "=l"(d) : "l"(a), "l"(b), "l"(c)); return d;
}
__device__ __forceinline__ ull add2(ull a, ull b) {
    ull d; asm("add.rn.f32x2 %0,%1,%2;" : "=l"(d) : "l"(a), "l"(b)); return d;
}
__device__ __forceinline__ ull relu2(ull t) {
    float lo, hi; unpack2(t, lo, hi);
    lo = fmaxf(lo, 0.f); hi = fmaxf(hi, 0.f);
    return pack2(lo, hi);
}

// ---------------- scratch ----------------
__device__ int     d_cnt[NN];
__device__ int     d_cur[NN];
__device__ int     d_off[NN + 1];
__device__ int     d_rows[EE];
__device__ int     d_bsum[NBLK];
__device__ int     d_gstart[GG + 1];
__device__ float   d_dinv[NN];
__device__ float4  d_xpad[NN];
__device__ float   d_xw1[NN * HH];
__device__ __half  d_yh[NN * HH];        // layer-1 messages, fp16 (gather traffic halved)
__device__ __half  d_y2h[NN * HH];       // layer-2 messages, fp16
__device__ float   d_xw2[NN * HH];
__device__ float   d_h2[NN * HH];
__device__ ull     d_Ppk[5 * 3 * HH];
__device__ ull     d_Qpk[5 * 3 * HH];
__device__ ull     d_Cpk[5 * HH];
__device__ float   d_Gf[CC * HH * HH];   // [320][32]
__device__ float   d_biasE[HH];
__device__ __half2 d_Rsh[NN * 160];      // 64MB — L2-resident

// ---------------- setup: fold & pack weights + zero counters ----------------
__global__ void setup_k(const float* __restrict__ fW, const float* __restrict__ fb,
                        const float* __restrict__ W1, const float* __restrict__ b1,
                        const float* __restrict__ W2, const float* __restrict__ b2,
                        const float* __restrict__ g1W) {
    int stride = blockDim.x * gridDim.x;
    int t0 = threadIdx.x + blockIdx.x * blockDim.x;
    for (int i = t0; i < NN; i += stride) { d_cnt[i] = 0; d_cur[i] = 0; }
    for (int t = t0; t < 5 * 3 * HH; t += stride) {
        int p = t / 96; int i = (t / 32) % 3; int h = t & 31;
        int c0 = 2 * p, c1 = 2 * p + 1;
        float pa0 = 0.f, pa1 = 0.f, qa0 = 0.f, qa1 = 0.f;
        for (int j = 0; j < HH; j++) {
            float w0 = fW[(c0 * 3 + i) * HH + j];
            float w1 = fW[(c1 * 3 + i) * HH + j];
            float u1 = W1[j * HH + h];
            float u2 = W1[(HH + j) * HH + h];
            pa0 += w0 * u1; pa1 += w1 * u1;
            qa0 += w0 * u2; qa1 += w1 * u2;
        }
        d_Ppk[t] = pack2(pa0, pa1);
        d_Qpk[t] = pack2(qa0, qa1);
    }
    for (int t = t0; t < 5 * HH; t += stride) {
        int p = t / 32; int h = t & 31;
        int c0 = 2 * p, c1 = 2 * p + 1;
        float s0 = b1[h], s1 = b1[h];
        for (int j = 0; j < HH; j++) {
            float u = W1[j * HH + h] + W1[(HH + j) * HH + h];
            s0 += fb[c0 * HH + j] * u;
            s1 += fb[c1 * HH + j] * u;
        }
        d_Cpk[t] = pack2(s0, s1);
    }
    for (int t = t0; t < CC * HH * HH; t += stride) {
        int c = t / (HH * HH); int i = (t / HH) % HH; int j = t & 31;
        float s = 0.f;
        for (int k = 0; k < HH; k++) s += W2[i * HH + k] * g1W[(3 + HH * c + k) * HH + j];
        d_Gf[t] = s;
    }
    for (int t = t0; t < HH; t += stride) {
        float s = 0.f;
        for (int c = 0; c < CC; c++)
            for (int k = 0; k < HH; k++) s += b2[k] * g1W[(3 + HH * c + k) * HH + t];
        d_biasE[t] = s;
    }
}

// ---------------- CSR build ----------------
__global__ void hist_k(const int* __restrict__ col) {
    int e = threadIdx.x + blockIdx.x * blockDim.x;
    if (e < EE) atomicAdd(&d_cnt[col[e]], 1);
}

__global__ void gstart_k(const int* __restrict__ batch) {
    int n = threadIdx.x + blockIdx.x * blockDim.x;
    if (n >= NN) return;
    int g = batch[n];
    int gp = n ? batch[n - 1] : -1;
    if (g != gp) for (int q = gp + 1; q <= g; q++) d_gstart[q] = n;
    if (n == NN - 1) for (int q = g + 1; q <= GG; q++) d_gstart[q] = NN;
}

__global__ void scanA_k() {
    __shared__ int wsum[32];
    int i = blockIdx.x * 1024 + threadIdx.x;
    int lane = threadIdx.x & 31, w = threadIdx.x >> 5;
    int v = (i < NN) ? d_cnt[i] : 0;
    #pragma unroll
    for (int d = 16; d > 0; d >>= 1) v += __shfl_down_sync(0xffffffffu, v, d);
    if (lane == 0) wsum[w] = v;
    __syncthreads();
    if (w == 0) {
        int s = wsum[lane];
        #pragma unroll
        for (int d = 16; d > 0; d >>= 1) s += __shfl_down_sync(0xffffffffu, s, d);
        if (lane == 0) d_bsum[blockIdx.x] = s;
    }
}
__global__ void scanB_k() {
    int lane = threadIdx.x;
    int carry = 0;
    for (int base = 0; base < NBLK; base += 32) {
        int i = base + lane;
        int v = (i < NBLK) ? d_bsum[i] : 0;
        int s = v;
        #pragma unroll
        for (int d = 1; d < 32; d <<= 1) {
            int u = __shfl_up_sync(0xffffffffu, s, d);
            if (lane >= d) s += u;
        }
        if (i < NBLK) d_bsum[i] = carry + s - v;
        carry += __shfl_sync(0xffffffffu, s, 31);
    }
}
__global__ void scanC_k() {
    __shared__ int wsum[32];
    int i = blockIdx.x * 1024 + threadIdx.x;
    int lane = threadIdx.x & 31, w = threadIdx.x >> 5;
    int v = (i < NN) ? d_cnt[i] : 0;
    int s = v;
    #pragma unroll
    for (int d = 1; d < 32; d <<= 1) {
        int u = __shfl_up_sync(0xffffffffu, s, d);
        if (lane >= d) s += u;
    }
    if (lane == 31) wsum[w] = s;
    __syncthreads();
    if (w == 0) {
        int t2 = wsum[lane];
        #pragma unroll
        for (int d = 1; d < 32; d <<= 1) {
            int u = __shfl_up_sync(0xffffffffu, t2, d);
            if (lane >= d) t2 += u;
        }
        wsum[lane] = t2;
    }
    __syncthreads();
    int base = d_bsum[blockIdx.x] + (w > 0 ? wsum[w - 1] : 0);
    if (i < NN) {
        d_off[i] = base + s - v;
        d_dinv[i] = rsqrtf((float)(v + 1));
    }
    if (i == NN - 1) d_off[NN] = base + s;
}

__global__ void fill_k(const int* __restrict__ row, const int* __restrict__ col) {
    int e = threadIdx.x + blockIdx.x * blockDim.x;
    if (e >= EE) return;
    int cn = col[e];
    int pos = atomicAdd(&d_cur[cn], 1);
    d_rows[d_off[cn] + pos] = row[e];
}

// ---------------- init: xpad + xw1 base ----------------
__global__ void init_k(const float* __restrict__ x, const float* __restrict__ g1W) {
    int t = threadIdx.x + blockIdx.x * blockDim.x;
    if (t >= NN * HH) return;
    int n = t >> 5; int h = t & 31;
    float x0 = x[n * 3 + 0], x1 = x[n * 3 + 1], x2 = x[n * 3 + 2];
    float indeg = (float)(d_off[n + 1] - d_off[n]);
    d_xw1[t] = x0 * g1W[h] + x1 * g1W[HH + h] + x2 * g1W[2 * HH + h] + indeg * d_biasE[h];
    if (h == 0) d_xpad[n] = make_float4(x0, x1, x2, 0.f);
}

// ---------------- fused 10-class edge MLP aggregation ----------------
__global__ void __launch_bounds__(256) edge_k() {
    __shared__ ull Qs[5 * 3 * HH];
    __shared__ ull Cs[5 * HH];
    for (int t = threadIdx.x; t < 5 * 3 * HH; t += blockDim.x) Qs[t] = d_Qpk[t];
    for (int t = threadIdx.x; t < 5 * HH; t += blockDim.x) Cs[t] = d_Cpk[t];
    __syncthreads();

    int lane = threadIdx.x & 31;
    int gw = (blockIdx.x * blockDim.x + threadIdx.x) >> 5;
    int nw = (gridDim.x * blockDim.x) >> 5;

    ull P0[5], P1[5], P2[5];
    #pragma unroll
    for (int p = 0; p < 5; p++) {
        P0[p] = d_Ppk[(p * 3 + 0) * HH + lane];
        P1[p] = d_Ppk[(p * 3 + 1) * HH + lane];
        P2[p] = d_Ppk[(p * 3 + 2) * HH + lane];
    }

    for (int n = gw; n < NN; n += nw) {
        float4 xn = d_xpad[n];
        ull xn0 = pack2(xn.x, xn.x), xn1 = pack2(xn.y, xn.y), xn2 = pack2(xn.z, xn.z);
        ull B[5], acc[5];
        #pragma unroll
        for (int p = 0; p < 5; p++) {
            ull b = fma2(xn0, Qs[(p * 3 + 0) * HH + lane], Cs[p * HH + lane]);
            b = fma2(xn1, Qs[(p * 3 + 1) * HH + lane], b);
            b = fma2(xn2, Qs[(p * 3 + 2) * HH + lane], b);
            B[p] = b;
            acc[p] = 0;
        }
        int k = d_off[n], ke = d_off[n + 1];
        for (; k + 2 <= ke; k += 2) {
            int r0 = __ldg(&d_rows[k]);
            int r1 = __ldg(&d_rows[k + 1]);
            float4 a = d_xpad[r0];
            float4 b4 = d_xpad[r1];
            ull a0 = pack2(a.x, a.x), a1 = pack2(a.y, a.y), a2 = pack2(a.z, a.z);
            ull c0 = pack2(b4.x, b4.x), c1 = pack2(b4.y, b4.y), c2 = pack2(b4.z, b4.z);
            #pragma unroll
            for (int p = 0; p < 5; p++) {
                ull t = fma2(a0, P0[p], B[p]);
                t = fma2(a1, P1[p], t);
                t = fma2(a2, P2[p], t);
                acc[p] = add2(acc[p], relu2(t));
                ull u = fma2(c0, P0[p], B[p]);
                u = fma2(c1, P1[p], u);
                u = fma2(c2, P2[p], u);
                acc[p] = add2(acc[p], relu2(u));
            }
        }
        if (k < ke) {
            int r0 = __ldg(&d_rows[k]);
            float4 a = d_xpad[r0];
            ull a0 = pack2(a.x, a.x), a1 = pack2(a.y, a.y), a2 = pack2(a.z, a.z);
            #pragma unroll
            for (int p = 0; p < 5; p++) {
                ull t = fma2(a0, P0[p], B[p]);
                t = fma2(a1, P1[p], t);
                t = fma2(a2, P2[p], t);
                acc[p] = add2(acc[p], relu2(t));
            }
        }
        __half2* rs = d_Rsh + n * 160;
        #pragma unroll
        for (int p = 0; p < 5; p++) {
            float lo, hi; unpack2(acc[p], lo, hi);
            rs[p * HH + lane] = __floats2half2_rn(lo, hi);
        }
    }
}

// ---------------- tiled GEMM: xw1 += Rs@Gf; yh = half(xw1*dinv) ----------------
__global__ void __launch_bounds__(256) gemm_k() {
    __shared__ float As[128][65];
    __shared__ float Gsh[64][HH];
    int t = threadIdx.x;
    int warp = t >> 5, lane = t & 31;
    int tx = t & 7, ty = t >> 3;
    int n0 = blockIdx.x * 128;
    ull acc[4][2];
    #pragma unroll
    for (int m = 0; m < 4; m++) { acc[m][0] = 0; acc[m][1] = 0; }

    for (int pc = 0; pc < 5; pc++) {
        __syncthreads();
        for (int i = t; i < 64 * HH; i += 256)
            Gsh[i >> 5][i & 31] = d_Gf[(pc * 64 + (i >> 5)) * HH + (i & 31)];
        #pragma unroll 4
        for (int it = 0; it < 16; it++) {
            int r = warp * 16 + it;
            int n = n0 + r;
            __half2 h = (n < NN) ? d_Rsh[n * 160 + pc * 32 + lane]
                                 : __floats2half2_rn(0.f, 0.f);
            As[r][lane] = __low2float(h);
            As[r][32 + lane] = __high2float(h);
        }
        __syncthreads();
        #pragma unroll 8
        for (int kk = 0; kk < 64; kk++) {
            float4 g4 = *(const float4*)&Gsh[kk][tx * 4];
            ull g0 = pack2(g4.x, g4.y), g1 = pack2(g4.z, g4.w);
            #pragma unroll
            for (int m = 0; m < 4; m++) {
                float a = As[ty * 4 + m][kk];
                ull ap = pack2(a, a);
                acc[m][0] = fma2(ap, g0, acc[m][0]);
                acc[m][1] = fma2(ap, g1, acc[m][1]);
            }
        }
    }
    #pragma unroll
    for (int m = 0; m < 4; m++) {
        int n = n0 + ty * 4 + m;
        if (n < NN) {
            float o0, o1, o2, o3;
            unpack2(acc[m][0], o0, o1);
            unpack2(acc[m][1], o2, o3);
            float4 cur = *(const float4*)&d_xw1[n * HH + tx * 4];
            o0 += cur.x; o1 += cur.y; o2 += cur.z; o3 += cur.w;
            *(float4*)&d_xw1[n * HH + tx * 4] = make_float4(o0, o1, o2, o3);
            float dv = d_dinv[n];
            __half2* yh2 = reinterpret_cast<__half2*>(d_yh);
            yh2[n * 16 + tx * 2]     = __floats2half2_rn(o0 * dv, o1 * dv);
            yh2[n * 16 + tx * 2 + 1] = __floats2half2_rn(o2 * dv, o3 * dv);
        }
    }
}

// ---------------- GCN1 gather (fp16 messages) + fused h1@gcn2_W -> xw2, y2h ----------------
__global__ void gcn1x_k(const float* __restrict__ g1b, const float* __restrict__ g2W) {
    __shared__ float Ws[HH * HH];
    for (int t = threadIdx.x; t < HH * HH; t += blockDim.x) Ws[t] = g2W[t];
    __syncthreads();
    int lane = threadIdx.x & 31;
    int n = blockIdx.x * (blockDim.x >> 5) + (threadIdx.x >> 5);
    if (n >= NN) return;
    int base = d_off[n], end = d_off[n + 1];
    float a0 = 0.f, a1 = 0.f, a2 = 0.f, a3 = 0.f;
    int k = base;
    for (; k + 4 <= end; k += 4) {
        int r0 = __ldg(&d_rows[k + 0]), r1 = __ldg(&d_rows[k + 1]);
        int r2 = __ldg(&d_rows[k + 2]), r3 = __ldg(&d_rows[k + 3]);
        a0 += __half2float(d_yh[r0 * HH + lane]);
        a1 += __half2float(d_yh[r1 * HH + lane]);
        a2 += __half2float(d_yh[r2 * HH + lane]);
        a3 += __half2float(d_yh[r3 * HH + lane]);
    }
    for (; k < end; k++) a0 += __half2float(d_yh[__ldg(&d_rows[k]) * HH + lane]);
    float acc = (a0 + a1) + (a2 + a3);
    float dv = d_dinv[n];
    float h1 = fmaxf(dv * acc + dv * dv * d_xw1[n * HH + lane] + g1b[lane], 0.f);
    float xw2 = 0.f;
    #pragma unroll
    for (int kk = 0; kk < HH; kk++)
        xw2 += __shfl_sync(0xffffffffu, h1, kk) * Ws[kk * HH + lane];
    d_xw2[n * HH + lane] = xw2;
    d_y2h[n * HH + lane] = __float2half(xw2 * dv);
}

// ---------------- GCN2 gather (fp16 messages) -> h2 ----------------
__global__ void gcn2_k(const float* __restrict__ g2b) {
    int lane = threadIdx.x & 31;
    int n = blockIdx.x * (blockDim.x >> 5) + (threadIdx.x >> 5);
    if (n >= NN) return;
    int base = d_off[n], end = d_off[n + 1];
    float a0 = 0.f, a1 = 0.f, a2 = 0.f, a3 = 0.f;
    int k = base;
    for (; k + 4 <= end; k += 4) {
        int r0 = __ldg(&d_rows[k + 0]), r1 = __ldg(&d_rows[k + 1]);
        int r2 = __ldg(&d_rows[k + 2]), r3 = __ldg(&d_rows[k + 3]);
        a0 += __half2float(d_y2h[r0 * HH + lane]);
        a1 += __half2float(d_y2h[r1 * HH + lane]);
        a2 += __half2float(d_y2h[r2 * HH + lane]);
        a3 += __half2float(d_y2h[r3 * HH + lane]);
    }
    for (; k < end; k++) a0 += __half2float(d_y2h[__ldg(&d_rows[k]) * HH + lane]);
    float acc = (a0 + a1) + (a2 + a3);
    float dv = d_dinv[n];
    float v = dv * acc + dv * dv * d_xw2[n * HH + lane] + g2b[lane];
    d_h2[n * HH + lane] = fmaxf(v, 0.f);
}

// ---------------- mean pool (per graph, no atomics) + classifier ----------------
__global__ void pool_cls_k(const float* __restrict__ clsW, const float* __restrict__ clsb,
                           float* __restrict__ out) {
    __shared__ float red[8][HH];
    __shared__ float pooled[HH];
    int g = blockIdx.x;
    int lane = threadIdx.x & 31, w = threadIdx.x >> 5;
    int s = d_gstart[g], e = d_gstart[g + 1];
    float acc = 0.f;
    for (int n = s + w; n < e; n += 8) acc += d_h2[n * HH + lane];
    red[w][lane] = acc;
    __syncthreads();
    if (w == 0) {
        float v = red[0][lane];
        #pragma unroll
        for (int i = 1; i < 8; i++) v += red[i][lane];
        float cnt = fmaxf((float)(e - s), 1.f);
        pooled[lane] = v / cnt;
    }
    __syncthreads();
    if (threadIdx.x < CC) {
        float sres = clsb[threadIdx.x];
        #pragma unroll
        for (int k2 = 0; k2 < HH; k2++) sres += pooled[k2] * clsW[k2 * CC + threadIdx.x];
        out[g * CC + threadIdx.x] = sres;
    }
}

// ---------------- launch ----------------
extern "C" void kernel_launch(void* const* d_in, const int* in_sizes, int n_in,
                              void* d_out, int out_size) {
    const float* x     = (const float*)d_in[0];
    const int*   ei    = (const int*)d_in[1];
    const int*   row   = ei;
    const int*   col   = ei + EE;
    const int*   batch = (const int*)d_in[2];
    const float* fW    = (const float*)d_in[3];
    const float* fb    = (const float*)d_in[4];
    const float* W1    = (const float*)d_in[5];
    const float* b1    = (const float*)d_in[6];
    const float* W2    = (const float*)d_in[7];
    const float* b2    = (const float*)d_in[8];
    const float* g1W   = (const float*)d_in[9];
    const float* g1b   = (const float*)d_in[10];
    const float* g2W   = (const float*)d_in[11];
    const float* g2b   = (const float*)d_in[12];
    const float* clsW  = (const float*)d_in[13];
    const float* clsb  = (const float*)d_in[14];
    float* out = (float*)d_out;

    const int TB = 256;
    const int gridE    = (EE + TB - 1) / TB;
    const int gridN    = (NN + TB - 1) / TB;
    const int gridN128 = (NN + 127) / 128;
    const int gridNH   = (NN * HH + TB - 1) / TB;

    setup_k<<<128, TB>>>(fW, fb, W1, b1, W2, b2, g1W);
    hist_k<<<gridE, TB>>>(col);
    gstart_k<<<gridN, TB>>>(batch);
    scanA_k<<<NBLK, 1024>>>();
    scanB_k<<<1, 32>>>();
    scanC_k<<<NBLK, 1024>>>();
    fill_k<<<gridE, TB>>>(row, col);
    init_k<<<gridNH, TB>>>(x, g1W);
    edge_k<<<1184, TB>>>();
    gemm_k<<<gridN128, TB>>>();
    gcn1x_k<<<(NN + 7) / 8, TB>>>(g1b, g2W);
    gcn2_k<<<(NN + 7) / 8, TB>>>(g2b);
    pool_cls_k<<<GG, TB>>>(clsW, clsb, out);
}

// round 15
// speedup vs baseline: 1.4375x; 1.0665x over previous
#include <cuda_runtime.h>
#include <cuda_fp16.h>

#define NN 100000
#define EE 1600000
#define HH 32
#define CC 10
#define GG 64
#define NBLK 98   // ceil(NN/1024)

typedef unsigned long long ull;

// ---------------- packed f32x2 helpers ----------------
__device__ __forceinline__ ull pack2(float lo, float hi) {
    ull r; asm("mov.b64 %0,{%1,%2};" : "=l"(r) : "f"(lo), "f"(hi)); return r;
}
__device__ __forceinline__ void unpack2(ull v, float& lo, float& hi) {
    asm("mov.b64 {%0,%1},%2;" : "=f"(lo), "=f"(hi) : "l"(v));
}
__device__ __forceinline__ ull fma2(ull a, ull b, ull c) {
    ull d; asm("fma.rn.f32x2 %0,%1,%2,%3;" : "=l"(d) : "l"(a), "l"(b), "l"(c)); return d;
}
__device__ __forceinline__ ull add2(ull a, ull b) {
    ull d; asm("add.rn.f32x2 %0,%1,%2;" : "=l"(d) : "l"(a), "l"(b)); return d;
}
__device__ __forceinline__ ull relu2(ull t) {
    float lo, hi; unpack2(t, lo, hi);
    lo = fmaxf(lo, 0.f); hi = fmaxf(hi, 0.f);
    return pack2(lo, hi);
}

// ---------------- scratch ----------------
__device__ int     d_cnt[NN];
__device__ int     d_cur[NN];
__device__ int     d_off[NN + 1];
__device__ int     d_rows[EE];
__device__ int     d_bsum[NBLK];
__device__ int     d_gstart[GG + 1];
__device__ float   d_dinv[NN];
__device__ float4  d_xpad[NN];
__device__ float   d_xw1[NN * HH];
__device__ __half  d_yh[NN * HH];        // layer-1 messages, fp16 (precision floor)
__device__ __half  d_y2h[NN * HH];       // layer-2 messages, fp16
__device__ float   d_xw2[NN * HH];
__device__ float   d_h2[NN * HH];
__device__ ull     d_Ppk[5 * 3 * HH];
__device__ ull     d_Qpk[5 * 3 * HH];
__device__ ull     d_Cpk[5 * HH];
__device__ float   d_Gf[CC * HH * HH];   // [320][32]
__device__ float   d_biasE[HH];
__device__ __half2 d_Rsh[NN * 160];      // 64MB — L2-resident

// ---------------- setup: fold & pack weights + zero counters ----------------
__global__ void setup_k(const float* __restrict__ fW, const float* __restrict__ fb,
                        const float* __restrict__ W1, const float* __restrict__ b1,
                        const float* __restrict__ W2, const float* __restrict__ b2,
                        const float* __restrict__ g1W) {
    int stride = blockDim.x * gridDim.x;
    int t0 = threadIdx.x + blockIdx.x * blockDim.x;
    for (int i = t0; i < NN; i += stride) { d_cnt[i] = 0; d_cur[i] = 0; }
    for (int t = t0; t < 5 * 3 * HH; t += stride) {
        int p = t / 96; int i = (t / 32) % 3; int h = t & 31;
        int c0 = 2 * p, c1 = 2 * p + 1;
        float pa0 = 0.f, pa1 = 0.f, qa0 = 0.f, qa1 = 0.f;
        for (int j = 0; j < HH; j++) {
            float w0 = fW[(c0 * 3 + i) * HH + j];
            float w1 = fW[(c1 * 3 + i) * HH + j];
            float u1 = W1[j * HH + h];
            float u2 = W1[(HH + j) * HH + h];
            pa0 += w0 * u1; pa1 += w1 * u1;
            qa0 += w0 * u2; qa1 += w1 * u2;
        }
        d_Ppk[t] = pack2(pa0, pa1);
        d_Qpk[t] = pack2(qa0, qa1);
    }
    for (int t = t0; t < 5 * HH; t += stride) {
        int p = t / 32; int h = t & 31;
        int c0 = 2 * p, c1 = 2 * p + 1;
        float s0 = b1[h], s1 = b1[h];
        for (int j = 0; j < HH; j++) {
            float u = W1[j * HH + h] + W1[(HH + j) * HH + h];
            s0 += fb[c0 * HH + j] * u;
            s1 += fb[c1 * HH + j] * u;
        }
        d_Cpk[t] = pack2(s0, s1);
    }
    for (int t = t0; t < CC * HH * HH; t += stride) {
        int c = t / (HH * HH); int i = (t / HH) % HH; int j = t & 31;
        float s = 0.f;
        for (int k = 0; k < HH; k++) s += W2[i * HH + k] * g1W[(3 + HH * c + k) * HH + j];
        d_Gf[t] = s;
    }
    for (int t = t0; t < HH; t += stride) {
        float s = 0.f;
        for (int c = 0; c < CC; c++)
            for (int k = 0; k < HH; k++) s += b2[k] * g1W[(3 + HH * c + k) * HH + t];
        d_biasE[t] = s;
    }
}

// ---------------- CSR build ----------------
__global__ void hist_k(const int* __restrict__ col) {
    int e = threadIdx.x + blockIdx.x * blockDim.x;
    if (e < EE) atomicAdd(&d_cnt[col[e]], 1);
}

__global__ void gstart_k(const int* __restrict__ batch) {
    int n = threadIdx.x + blockIdx.x * blockDim.x;
    if (n >= NN) return;
    int g = batch[n];
    int gp = n ? batch[n - 1] : -1;
    if (g != gp) for (int q = gp + 1; q <= g; q++) d_gstart[q] = n;
    if (n == NN - 1) for (int q = g + 1; q <= GG; q++) d_gstart[q] = NN;
}

__global__ void scanA_k() {
    __shared__ int wsum[32];
    int i = blockIdx.x * 1024 + threadIdx.x;
    int lane = threadIdx.x & 31, w = threadIdx.x >> 5;
    int v = (i < NN) ? d_cnt[i] : 0;
    #pragma unroll
    for (int d = 16; d > 0; d >>= 1) v += __shfl_down_sync(0xffffffffu, v, d);
    if (lane == 0) wsum[w] = v;
    __syncthreads();
    if (w == 0) {
        int s = wsum[lane];
        #pragma unroll
        for (int d = 16; d > 0; d >>= 1) s += __shfl_down_sync(0xffffffffu, s, d);
        if (lane == 0) d_bsum[blockIdx.x] = s;
    }
}
__global__ void scanB_k() {
    int lane = threadIdx.x;
    int carry = 0;
    for (int base = 0; base < NBLK; base += 32) {
        int i = base + lane;
        int v = (i < NBLK) ? d_bsum[i] : 0;
        int s = v;
        #pragma unroll
        for (int d = 1; d < 32; d <<= 1) {
            int u = __shfl_up_sync(0xffffffffu, s, d);
            if (lane >= d) s += u;
        }
        if (i < NBLK) d_bsum[i] = carry + s - v;
        carry += __shfl_sync(0xffffffffu, s, 31);
    }
}
__global__ void scanC_k() {
    __shared__ int wsum[32];
    int i = blockIdx.x * 1024 + threadIdx.x;
    int lane = threadIdx.x & 31, w = threadIdx.x >> 5;
    int v = (i < NN) ? d_cnt[i] : 0;
    int s = v;
    #pragma unroll
    for (int d = 1; d < 32; d <<= 1) {
        int u = __shfl_up_sync(0xffffffffu, s, d);
        if (lane >= d) s += u;
    }
    if (lane == 31) wsum[w] = s;
    __syncthreads();
    if (w == 0) {
        int t2 = wsum[lane];
        #pragma unroll
        for (int d = 1; d < 32; d <<= 1) {
            int u = __shfl_up_sync(0xffffffffu, t2, d);
            if (lane >= d) t2 += u;
        }
        wsum[lane] = t2;
    }
    __syncthreads();
    int base = d_bsum[blockIdx.x] + (w > 0 ? wsum[w - 1] : 0);
    if (i < NN) {
        d_off[i] = base + s - v;
        d_dinv[i] = rsqrtf((float)(v + 1));
    }
    if (i == NN - 1) d_off[NN] = base + s;
}

__global__ void fill_k(const int* __restrict__ row, const int* __restrict__ col) {
    int e = threadIdx.x + blockIdx.x * blockDim.x;
    if (e >= EE) return;
    int cn = col[e];
    int pos = atomicAdd(&d_cur[cn], 1);
    d_rows[d_off[cn] + pos] = row[e];
}

// ---------------- init: xpad + xw1 base ----------------
__global__ void init_k(const float* __restrict__ x, const float* __restrict__ g1W) {
    int t = threadIdx.x + blockIdx.x * blockDim.x;
    if (t >= NN * HH) return;
    int n = t >> 5; int h = t & 31;
    float x0 = x[n * 3 + 0], x1 = x[n * 3 + 1], x2 = x[n * 3 + 2];
    float indeg = (float)(d_off[n + 1] - d_off[n]);
    d_xw1[t] = x0 * g1W[h] + x1 * g1W[HH + h] + x2 * g1W[2 * HH + h] + indeg * d_biasE[h];
    if (h == 0) d_xpad[n] = make_float4(x0, x1, x2, 0.f);
}

// ---------------- fused 10-class edge MLP aggregation (4-edge unroll) ----------------
__global__ void __launch_bounds__(256) edge_k() {
    __shared__ ull Qs[5 * 3 * HH];
    __shared__ ull Cs[5 * HH];
    for (int t = threadIdx.x; t < 5 * 3 * HH; t += blockDim.x) Qs[t] = d_Qpk[t];
    for (int t = threadIdx.x; t < 5 * HH; t += blockDim.x) Cs[t] = d_Cpk[t];
    __syncthreads();

    int lane = threadIdx.x & 31;
    int gw = (blockIdx.x * blockDim.x + threadIdx.x) >> 5;
    int nw = (gridDim.x * blockDim.x) >> 5;

    ull P0[5], P1[5], P2[5];
    #pragma unroll
    for (int p = 0; p < 5; p++) {
        P0[p] = d_Ppk[(p * 3 + 0) * HH + lane];
        P1[p] = d_Ppk[(p * 3 + 1) * HH + lane];
        P2[p] = d_Ppk[(p * 3 + 2) * HH + lane];
    }

    for (int n = gw; n < NN; n += nw) {
        float4 xn = d_xpad[n];
        ull xn0 = pack2(xn.x, xn.x), xn1 = pack2(xn.y, xn.y), xn2 = pack2(xn.z, xn.z);
        ull B[5], acc[5];
        #pragma unroll
        for (int p = 0; p < 5; p++) {
            ull b = fma2(xn0, Qs[(p * 3 + 0) * HH + lane], Cs[p * HH + lane]);
            b = fma2(xn1, Qs[(p * 3 + 1) * HH + lane], b);
            b = fma2(xn2, Qs[(p * 3 + 2) * HH + lane], b);
            B[p] = b;
            acc[p] = 0;
        }
        int k = d_off[n], ke = d_off[n + 1];
        for (; k + 4 <= ke; k += 4) {
            int r0 = __ldg(&d_rows[k + 0]);
            int r1 = __ldg(&d_rows[k + 1]);
            int r2 = __ldg(&d_rows[k + 2]);
            int r3 = __ldg(&d_rows[k + 3]);
            float4 a = d_xpad[r0];
            float4 b4 = d_xpad[r1];
            float4 c4 = d_xpad[r2];
            float4 d4 = d_xpad[r3];
            ull a0 = pack2(a.x, a.x),  a1 = pack2(a.y, a.y),  a2 = pack2(a.z, a.z);
            ull c0 = pack2(b4.x, b4.x), c1 = pack2(b4.y, b4.y), c2 = pack2(b4.z, b4.z);
            ull e0 = pack2(c4.x, c4.x), e1 = pack2(c4.y, c4.y), e2 = pack2(c4.z, c4.z);
            ull f0 = pack2(d4.x, d4.x), f1 = pack2(d4.y, d4.y), f2 = pack2(d4.z, d4.z);
            #pragma unroll
            for (int p = 0; p < 5; p++) {
                ull t = fma2(a0, P0[p], B[p]);
                t = fma2(a1, P1[p], t);
                t = fma2(a2, P2[p], t);
                ull u = fma2(c0, P0[p], B[p]);
                u = fma2(c1, P1[p], u);
                u = fma2(c2, P2[p], u);
                ull v = fma2(e0, P0[p], B[p]);
                v = fma2(e1, P1[p], v);
                v = fma2(e2, P2[p], v);
                ull w = fma2(f0, P0[p], B[p]);
                w = fma2(f1, P1[p], w);
                w = fma2(f2, P2[p], w);
                acc[p] = add2(acc[p], add2(add2(relu2(t), relu2(u)),
                                           add2(relu2(v), relu2(w))));
            }
        }
        for (; k < ke; k++) {
            int r0 = __ldg(&d_rows[k]);
            float4 a = d_xpad[r0];
            ull a0 = pack2(a.x, a.x), a1 = pack2(a.y, a.y), a2 = pack2(a.z, a.z);
            #pragma unroll
            for (int p = 0; p < 5; p++) {
                ull t = fma2(a0, P0[p], B[p]);
                t = fma2(a1, P1[p], t);
                t = fma2(a2, P2[p], t);
                acc[p] = add2(acc[p], relu2(t));
            }
        }
        __half2* rs = d_Rsh + n * 160;
        #pragma unroll
        for (int p = 0; p < 5; p++) {
            float lo, hi; unpack2(acc[p], lo, hi);
            rs[p * HH + lane] = __floats2half2_rn(lo, hi);
        }
    }
}

// ---------------- tiled GEMM: xw1 += Rs@Gf; yh = half(xw1*dinv) ----------------
__global__ void __launch_bounds__(256) gemm_k() {
    __shared__ float As[128][65];
    __shared__ float Gsh[64][HH];
    int t = threadIdx.x;
    int warp = t >> 5, lane = t & 31;
    int tx = t & 7, ty = t >> 3;
    int n0 = blockIdx.x * 128;
    ull acc[4][2];
    #pragma unroll
    for (int m = 0; m < 4; m++) { acc[m][0] = 0; acc[m][1] = 0; }

    for (int pc = 0; pc < 5; pc++) {
        __syncthreads();
        for (int i = t; i < 64 * HH; i += 256)
            Gsh[i >> 5][i & 31] = d_Gf[(pc * 64 + (i >> 5)) * HH + (i & 31)];
        #pragma unroll 4
        for (int it = 0; it < 16; it++) {
            int r = warp * 16 + it;
            int n = n0 + r;
            __half2 h = (n < NN) ? d_Rsh[n * 160 + pc * 32 + lane]
                                 : __floats2half2_rn(0.f, 0.f);
            As[r][lane] = __low2float(h);
            As[r][32 + lane] = __high2float(h);
        }
        __syncthreads();
        #pragma unroll 8
        for (int kk = 0; kk < 64; kk++) {
            float4 g4 = *(const float4*)&Gsh[kk][tx * 4];
            ull g0 = pack2(g4.x, g4.y), g1 = pack2(g4.z, g4.w);
            #pragma unroll
            for (int m = 0; m < 4; m++) {
                float a = As[ty * 4 + m][kk];
                ull ap = pack2(a, a);
                acc[m][0] = fma2(ap, g0, acc[m][0]);
                acc[m][1] = fma2(ap, g1, acc[m][1]);
            }
        }
    }
    #pragma unroll
    for (int m = 0; m < 4; m++) {
        int n = n0 + ty * 4 + m;
        if (n < NN) {
            float o0, o1, o2, o3;
            unpack2(acc[m][0], o0, o1);
            unpack2(acc[m][1], o2, o3);
            float4 cur = *(const float4*)&d_xw1[n * HH + tx * 4];
            o0 += cur.x; o1 += cur.y; o2 += cur.z; o3 += cur.w;
            *(float4*)&d_xw1[n * HH + tx * 4] = make_float4(o0, o1, o2, o3);
            float dv = d_dinv[n];
            __half2* yh2 = reinterpret_cast<__half2*>(d_yh);
            yh2[n * 16 + tx * 2]     = __floats2half2_rn(o0 * dv, o1 * dv);
            yh2[n * 16 + tx * 2 + 1] = __floats2half2_rn(o2 * dv, o3 * dv);
        }
    }
}

// ---------------- GCN1 gather (fp16 messages) + fused h1@gcn2_W -> xw2, y2h ----------------
__global__ void gcn1x_k(const float* __restrict__ g1b, const float* __restrict__ g2W) {
    __shared__ float Ws[HH * HH];
    for (int t = threadIdx.x; t < HH * HH; t += blockDim.x) Ws[t] = g2W[t];
    __syncthreads();
    int lane = threadIdx.x & 31;
    int n = blockIdx.x * (blockDim.x >> 5) + (threadIdx.x >> 5);
    if (n >= NN) return;
    int base = d_off[n], end = d_off[n + 1];
    float a0 = 0.f, a1 = 0.f, a2 = 0.f, a3 = 0.f;
    int k = base;
    for (; k + 4 <= end; k += 4) {
        int r0 = __ldg(&d_rows[k + 0]), r1 = __ldg(&d_rows[k + 1]);
        int r2 = __ldg(&d_rows[k + 2]), r3 = __ldg(&d_rows[k + 3]);
        a0 += __half2float(d_yh[r0 * HH + lane]);
        a1 += __half2float(d_yh[r1 * HH + lane]);
        a2 += __half2float(d_yh[r2 * HH + lane]);
        a3 += __half2float(d_yh[r3 * HH + lane]);
    }
    for (; k < end; k++) a0 += __half2float(d_yh[__ldg(&d_rows[k]) * HH + lane]);
    float acc = (a0 + a1) + (a2 + a3);
    float dv = d_dinv[n];
    float h1 = fmaxf(dv * acc + dv * dv * d_xw1[n * HH + lane] + g1b[lane], 0.f);
    float xw2 = 0.f;
    #pragma unroll
    for (int kk = 0; kk < HH; kk++)
        xw2 += __shfl_sync(0xffffffffu, h1, kk) * Ws[kk * HH + lane];
    d_xw2[n * HH + lane] = xw2;
    d_y2h[n * HH + lane] = __float2half(xw2 * dv);
}

// ---------------- GCN2 gather (fp16 messages) -> h2 ----------------
__global__ void gcn2_k(const float* __restrict__ g2b) {
    int lane = threadIdx.x & 31;
    int n = blockIdx.x * (blockDim.x >> 5) + (threadIdx.x >> 5);
    if (n >= NN) return;
    int base = d_off[n], end = d_off[n + 1];
    float a0 = 0.f, a1 = 0.f, a2 = 0.f, a3 = 0.f;
    int k = base;
    for (; k + 4 <= end; k += 4) {
        int r0 = __ldg(&d_rows[k + 0]), r1 = __ldg(&d_rows[k + 1]);
        int r2 = __ldg(&d_rows[k + 2]), r3 = __ldg(&d_rows[k + 3]);
        a0 += __half2float(d_y2h[r0 * HH + lane]);
        a1 += __half2float(d_y2h[r1 * HH + lane]);
        a2 += __half2float(d_y2h[r2 * HH + lane]);
        a3 += __half2float(d_y2h[r3 * HH + lane]);
    }
    for (; k < end; k++) a0 += __half2float(d_y2h[__ldg(&d_rows[k]) * HH + lane]);
    float acc = (a0 + a1) + (a2 + a3);
    float dv = d_dinv[n];
    float v = dv * acc + dv * dv * d_xw2[n * HH + lane] + g2b[lane];
    d_h2[n * HH + lane] = fmaxf(v, 0.f);
}

// ---------------- mean pool (per graph, no atomics) + classifier ----------------
__global__ void pool_cls_k(const float* __restrict__ clsW, const float* __restrict__ clsb,
                           float* __restrict__ out) {
    __shared__ float red[8][HH];
    __shared__ float pooled[HH];
    int g = blockIdx.x;
    int lane = threadIdx.x & 31, w = threadIdx.x >> 5;
    int s = d_gstart[g], e = d_gstart[g + 1];
    float acc = 0.f;
    for (int n = s + w; n < e; n += 8) acc += d_h2[n * HH + lane];
    red[w][lane] = acc;
    __syncthreads();
    if (w == 0) {
        float v = red[0][lane];
        #pragma unroll
        for (int i = 1; i < 8; i++) v += red[i][lane];
        float cnt = fmaxf((float)(e - s), 1.f);
        pooled[lane] = v / cnt;
    }
    __syncthreads();
    if (threadIdx.x < CC) {
        float sres = clsb[threadIdx.x];
        #pragma unroll
        for (int k2 = 0; k2 < HH; k2++) sres += pooled[k2] * clsW[k2 * CC + threadIdx.x];
        out[g * CC + threadIdx.x] = sres;
    }
}

// ---------------- launch ----------------
extern "C" void kernel_launch(void* const* d_in, const int* in_sizes, int n_in,
                              void* d_out, int out_size) {
    const float* x     = (const float*)d_in[0];
    const int*   ei    = (const int*)d_in[1];
    const int*   row   = ei;
    const int*   col   = ei + EE;
    const int*   batch = (const int*)d_in[2];
    const float* fW    = (const float*)d_in[3];
    const float* fb    = (const float*)d_in[4];
    const float* W1    = (const float*)d_in[5];
    const float* b1    = (const float*)d_in[6];
    const float* W2    = (const float*)d_in[7];
    const float* b2    = (const float*)d_in[8];
    const float* g1W   = (const float*)d_in[9];
    const float* g1b   = (const float*)d_in[10];
    const float* g2W   = (const float*)d_in[11];
    const float* g2b   = (const float*)d_in[12];
    const float* clsW  = (const float*)d_in[13];
    const float* clsb  = (const float*)d_in[14];
    float* out = (float*)d_out;

    const int TB = 256;
    const int gridE    = (EE + TB - 1) / TB;
    const int gridN    = (NN + TB - 1) / TB;
    const int gridN128 = (NN + 127) / 128;
    const int gridNH   = (NN * HH + TB - 1) / TB;

    setup_k<<<128, TB>>>(fW, fb, W1, b1, W2, b2, g1W);
    hist_k<<<gridE, TB>>>(col);
    gstart_k<<<gridN, TB>>>(batch);
    scanA_k<<<NBLK, 1024>>>();
    scanB_k<<<1, 32>>>();
    scanC_k<<<NBLK, 1024>>>();
    fill_k<<<gridE, TB>>>(row, col);
    init_k<<<gridNH, TB>>>(x, g1W);
    edge_k<<<1184, TB>>>();
    gemm_k<<<gridN128, TB>>>();
    gcn1x_k<<<(NN + 7) / 8, TB>>>(g1b, g2W);
    gcn2_k<<<(NN + 7) / 8, TB>>>(g2b);
    pool_cls_k<<<GG, TB>>>(clsW, clsb, out);
}

// round 16
// speedup vs baseline: 1.4646x; 1.0188x over previous
#include <cuda_runtime.h>
#include <cuda_fp16.h>

#define NN 100000
#define EE 1600000
#define HH 32
#define CC 10
#define GG 64
#define NBLK 98   // ceil(NN/1024)

typedef unsigned long long ull;

// ---------------- packed f32x2 helpers ----------------
__device__ __forceinline__ ull pack2(float lo, float hi) {
    ull r; asm("mov.b64 %0,{%1,%2};" : "=l"(r) : "f"(lo), "f"(hi)); return r;
}
__device__ __forceinline__ void unpack2(ull v, float& lo, float& hi) {
    asm("mov.b64 {%0,%1},%2;" : "=f"(lo), "=f"(hi) : "l"(v));
}
__device__ __forceinline__ ull fma2(ull a, ull b, ull c) {
    ull d; asm("fma.rn.f32x2 %0,%1,%2,%3;" : "=l"(d) : "l"(a), "l"(b), "l"(c)); return d;
}
__device__ __forceinline__ ull add2(ull a, ull b) {
    ull d; asm("add.rn.f32x2 %0,%1,%2;" : "=l"(d) : "l"(a), "l"(b)); return d;
}
__device__ __forceinline__ ull relu2(ull t) {
    float lo, hi; unpack2(t, lo, hi);
    lo = fmaxf(lo, 0.f); hi = fmaxf(hi, 0.f);
    return pack2(lo, hi);
}

// ---------------- scratch ----------------
__device__ int     d_cnt[NN];
__device__ int     d_cur[NN];
__device__ int     d_off[NN + 1];
__device__ int     d_rows[EE];
__device__ int     d_bsum[NBLK];
__device__ float   d_dinv[NN];
__device__ float4  d_xpad[NN];
__device__ float   d_xw1[NN * HH];
__device__ __half  d_yh[NN * HH];        // layer-1 messages, fp16
__device__ __half  d_y2h[NN * HH];       // layer-2 messages, fp16
__device__ float   d_xw2[NN * HH];
__device__ float   d_pooled[GG * HH];
__device__ ull     d_Ppk[5 * 3 * HH];
__device__ ull     d_Qpk[5 * 3 * HH];
__device__ ull     d_Cpk[5 * HH];
__device__ float   d_Gf[CC * HH * HH];   // [320][32]
__device__ float   d_biasE[HH];
__device__ __half2 d_Rsh[NN * 160];      // 64MB — L2-resident

// ---------------- setup: fold & pack weights + zero counters/pooled ----------------
__global__ void setup_k(const float* __restrict__ fW, const float* __restrict__ fb,
                        const float* __restrict__ W1, const float* __restrict__ b1,
                        const float* __restrict__ W2, const float* __restrict__ b2,
                        const float* __restrict__ g1W) {
    int stride = blockDim.x * gridDim.x;
    int t0 = threadIdx.x + blockIdx.x * blockDim.x;
    for (int i = t0; i < NN; i += stride) { d_cnt[i] = 0; d_cur[i] = 0; }
    for (int i = t0; i < GG * HH; i += stride) d_pooled[i] = 0.f;
    for (int t = t0; t < 5 * 3 * HH; t += stride) {
        int p = t / 96; int i = (t / 32) % 3; int h = t & 31;
        int c0 = 2 * p, c1 = 2 * p + 1;
        float pa0 = 0.f, pa1 = 0.f, qa0 = 0.f, qa1 = 0.f;
        for (int j = 0; j < HH; j++) {
            float w0 = fW[(c0 * 3 + i) * HH + j];
            float w1 = fW[(c1 * 3 + i) * HH + j];
            float u1 = W1[j * HH + h];
            float u2 = W1[(HH + j) * HH + h];
            pa0 += w0 * u1; pa1 += w1 * u1;
            qa0 += w0 * u2; qa1 += w1 * u2;
        }
        d_Ppk[t] = pack2(pa0, pa1);
        d_Qpk[t] = pack2(qa0, qa1);
    }
    for (int t = t0; t < 5 * HH; t += stride) {
        int p = t / 32; int h = t & 31;
        int c0 = 2 * p, c1 = 2 * p + 1;
        float s0 = b1[h], s1 = b1[h];
        for (int j = 0; j < HH; j++) {
            float u = W1[j * HH + h] + W1[(HH + j) * HH + h];
            s0 += fb[c0 * HH + j] * u;
            s1 += fb[c1 * HH + j] * u;
        }
        d_Cpk[t] = pack2(s0, s1);
    }
    for (int t = t0; t < CC * HH * HH; t += stride) {
        int c = t / (HH * HH); int i = (t / HH) % HH; int j = t & 31;
        float s = 0.f;
        for (int k = 0; k < HH; k++) s += W2[i * HH + k] * g1W[(3 + HH * c + k) * HH + j];
        d_Gf[t] = s;
    }
    for (int t = t0; t < HH; t += stride) {
        float s = 0.f;
        for (int c = 0; c < CC; c++)
            for (int k = 0; k < HH; k++) s += b2[k] * g1W[(3 + HH * c + k) * HH + t];
        d_biasE[t] = s;
    }
}

// ---------------- CSR build ----------------
__global__ void hist_k(const int* __restrict__ col) {
    int e = threadIdx.x + blockIdx.x * blockDim.x;
    if (e < EE) atomicAdd(&d_cnt[col[e]], 1);
}

__global__ void scanA_k() {
    __shared__ int wsum[32];
    int i = blockIdx.x * 1024 + threadIdx.x;
    int lane = threadIdx.x & 31, w = threadIdx.x >> 5;
    int v = (i < NN) ? d_cnt[i] : 0;
    #pragma unroll
    for (int d = 16; d > 0; d >>= 1) v += __shfl_down_sync(0xffffffffu, v, d);
    if (lane == 0) wsum[w] = v;
    __syncthreads();
    if (w == 0) {
        int s = wsum[lane];
        #pragma unroll
        for (int d = 16; d > 0; d >>= 1) s += __shfl_down_sync(0xffffffffu, s, d);
        if (lane == 0) d_bsum[blockIdx.x] = s;
    }
}
__global__ void scanB_k() {
    int lane = threadIdx.x;
    int carry = 0;
    for (int base = 0; base < NBLK; base += 32) {
        int i = base + lane;
        int v = (i < NBLK) ? d_bsum[i] : 0;
        int s = v;
        #pragma unroll
        for (int d = 1; d < 32; d <<= 1) {
            int u = __shfl_up_sync(0xffffffffu, s, d);
            if (lane >= d) s += u;
        }
        if (i < NBLK) d_bsum[i] = carry + s - v;
        carry += __shfl_sync(0xffffffffu, s, 31);
    }
}
// scanC + xpad/dinv init
__global__ void scanC_k(const float* __restrict__ x) {
    __shared__ int wsum[32];
    int i = blockIdx.x * 1024 + threadIdx.x;
    int lane = threadIdx.x & 31, w = threadIdx.x >> 5;
    int v = (i < NN) ? d_cnt[i] : 0;
    int s = v;
    #pragma unroll
    for (int d = 1; d < 32; d <<= 1) {
        int u = __shfl_up_sync(0xffffffffu, s, d);
        if (lane >= d) s += u;
    }
    if (lane == 31) wsum[w] = s;
    __syncthreads();
    if (w == 0) {
        int t2 = wsum[lane];
        #pragma unroll
        for (int d = 1; d < 32; d <<= 1) {
            int u = __shfl_up_sync(0xffffffffu, t2, d);
            if (lane >= d) t2 += u;
        }
        wsum[lane] = t2;
    }
    __syncthreads();
    int base = d_bsum[blockIdx.x] + (w > 0 ? wsum[w - 1] : 0);
    if (i < NN) {
        d_off[i] = base + s - v;
        d_dinv[i] = rsqrtf((float)(v + 1));
        float x0 = x[i * 3 + 0], x1 = x[i * 3 + 1], x2 = x[i * 3 + 2];
        d_xpad[i] = make_float4(x0, x1, x2, (float)v);   // .w = indeg
    }
    if (i == NN - 1) d_off[NN] = base + s;
}

__global__ void fill_k(const int* __restrict__ row, const int* __restrict__ col) {
    int e = threadIdx.x + blockIdx.x * blockDim.x;
    if (e >= EE) return;
    int cn = col[e];
    int pos = atomicAdd(&d_cur[cn], 1);
    d_rows[d_off[cn] + pos] = row[e];
}

// ---------------- fused 10-class edge MLP aggregation (4-edge unroll) ----------------
__global__ void __launch_bounds__(256) edge_k() {
    __shared__ ull Qs[5 * 3 * HH];
    __shared__ ull Cs[5 * HH];
    for (int t = threadIdx.x; t < 5 * 3 * HH; t += blockDim.x) Qs[t] = d_Qpk[t];
    for (int t = threadIdx.x; t < 5 * HH; t += blockDim.x) Cs[t] = d_Cpk[t];
    __syncthreads();

    int lane = threadIdx.x & 31;
    int gw = (blockIdx.x * blockDim.x + threadIdx.x) >> 5;
    int nw = (gridDim.x * blockDim.x) >> 5;

    ull P0[5], P1[5], P2[5];
    #pragma unroll
    for (int p = 0; p < 5; p++) {
        P0[p] = d_Ppk[(p * 3 + 0) * HH + lane];
        P1[p] = d_Ppk[(p * 3 + 1) * HH + lane];
        P2[p] = d_Ppk[(p * 3 + 2) * HH + lane];
    }

    for (int n = gw; n < NN; n += nw) {
        float4 xn = d_xpad[n];
        ull xn0 = pack2(xn.x, xn.x), xn1 = pack2(xn.y, xn.y), xn2 = pack2(xn.z, xn.z);
        ull B[5], acc[5];
        #pragma unroll
        for (int p = 0; p < 5; p++) {
            ull b = fma2(xn0, Qs[(p * 3 + 0) * HH + lane], Cs[p * HH + lane]);
            b = fma2(xn1, Qs[(p * 3 + 1) * HH + lane], b);
            b = fma2(xn2, Qs[(p * 3 + 2) * HH + lane], b);
            B[p] = b;
            acc[p] = 0;
        }
        int k = d_off[n], ke = d_off[n + 1];
        for (; k + 4 <= ke; k += 4) {
            int r0 = __ldg(&d_rows[k + 0]);
            int r1 = __ldg(&d_rows[k + 1]);
            int r2 = __ldg(&d_rows[k + 2]);
            int r3 = __ldg(&d_rows[k + 3]);
            float4 a = d_xpad[r0];
            float4 b4 = d_xpad[r1];
            float4 c4 = d_xpad[r2];
            float4 d4 = d_xpad[r3];
            ull a0 = pack2(a.x, a.x),  a1 = pack2(a.y, a.y),  a2 = pack2(a.z, a.z);
            ull c0 = pack2(b4.x, b4.x), c1 = pack2(b4.y, b4.y), c2 = pack2(b4.z, b4.z);
            ull e0 = pack2(c4.x, c4.x), e1 = pack2(c4.y, c4.y), e2 = pack2(c4.z, c4.z);
            ull f0 = pack2(d4.x, d4.x), f1 = pack2(d4.y, d4.y), f2 = pack2(d4.z, d4.z);
            #pragma unroll
            for (int p = 0; p < 5; p++) {
                ull t = fma2(a0, P0[p], B[p]);
                t = fma2(a1, P1[p], t);
                t = fma2(a2, P2[p], t);
                ull u = fma2(c0, P0[p], B[p]);
                u = fma2(c1, P1[p], u);
                u = fma2(c2, P2[p], u);
                ull v = fma2(e0, P0[p], B[p]);
                v = fma2(e1, P1[p], v);
                v = fma2(e2, P2[p], v);
                ull w = fma2(f0, P0[p], B[p]);
                w = fma2(f1, P1[p], w);
                w = fma2(f2, P2[p], w);
                acc[p] = add2(acc[p], add2(add2(relu2(t), relu2(u)),
                                           add2(relu2(v), relu2(w))));
            }
        }
        for (; k < ke; k++) {
            int r0 = __ldg(&d_rows[k]);
            float4 a = d_xpad[r0];
            ull a0 = pack2(a.x, a.x), a1 = pack2(a.y, a.y), a2 = pack2(a.z, a.z);
            #pragma unroll
            for (int p = 0; p < 5; p++) {
                ull t = fma2(a0, P0[p], B[p]);
                t = fma2(a1, P1[p], t);
                t = fma2(a2, P2[p], t);
                acc[p] = add2(acc[p], relu2(t));
            }
        }
        __half2* rs = d_Rsh + n * 160;
        #pragma unroll
        for (int p = 0; p < 5; p++) {
            float lo, hi; unpack2(acc[p], lo, hi);
            rs[p * HH + lane] = __floats2half2_rn(lo, hi);
        }
    }
}

// ---------------- tiled GEMM: xw1 = base(x,indeg) + Rs@Gf; yh = half(xw1*dinv) ----------------
__global__ void __launch_bounds__(256) gemm_k(const float* __restrict__ g1W) {
    __shared__ float As[128][65];
    __shared__ float Gsh[64][HH];
    __shared__ float4 xb[128];
    __shared__ float g1s[3 * HH];
    __shared__ float bEs[HH];
    int t = threadIdx.x;
    int warp = t >> 5, lane = t & 31;
    int tx = t & 7, ty = t >> 3;
    int n0 = blockIdx.x * 128;
    if (t < 96) g1s[t] = g1W[t];
    if (t < HH) bEs[t] = d_biasE[t];
    if (t < 128) {
        int n = n0 + t;
        xb[t] = (n < NN) ? d_xpad[n] : make_float4(0.f, 0.f, 0.f, 0.f);
    }
    ull acc[4][2];
    #pragma unroll
    for (int m = 0; m < 4; m++) { acc[m][0] = 0; acc[m][1] = 0; }

    for (int pc = 0; pc < 5; pc++) {
        __syncthreads();
        for (int i = t; i < 64 * HH; i += 256)
            Gsh[i >> 5][i & 31] = d_Gf[(pc * 64 + (i >> 5)) * HH + (i & 31)];
        #pragma unroll 4
        for (int it = 0; it < 16; it++) {
            int r = warp * 16 + it;
            int n = n0 + r;
            __half2 h = (n < NN) ? d_Rsh[n * 160 + pc * 32 + lane]
                                 : __floats2half2_rn(0.f, 0.f);
            As[r][lane] = __low2float(h);
            As[r][32 + lane] = __high2float(h);
        }
        __syncthreads();
        #pragma unroll 8
        for (int kk = 0; kk < 64; kk++) {
            float4 g4 = *(const float4*)&Gsh[kk][tx * 4];
            ull g0 = pack2(g4.x, g4.y), g1 = pack2(g4.z, g4.w);
            #pragma unroll
            for (int m = 0; m < 4; m++) {
                float a = As[ty * 4 + m][kk];
                ull ap = pack2(a, a);
                acc[m][0] = fma2(ap, g0, acc[m][0]);
                acc[m][1] = fma2(ap, g1, acc[m][1]);
            }
        }
    }
    #pragma unroll
    for (int m = 0; m < 4; m++) {
        int r = ty * 4 + m;
        int n = n0 + r;
        if (n < NN) {
            float o[4];
            unpack2(acc[m][0], o[0], o[1]);
            unpack2(acc[m][1], o[2], o[3]);
            float4 xr = xb[r];
            #pragma unroll
            for (int j = 0; j < 4; j++) {
                int col = tx * 4 + j;
                o[j] += xr.x * g1s[col] + xr.y * g1s[HH + col] + xr.z * g1s[2 * HH + col]
                      + xr.w * bEs[col];
            }
            *(float4*)&d_xw1[n * HH + tx * 4] = make_float4(o[0], o[1], o[2], o[3]);
            float dv = d_dinv[n];
            __half2* yh2 = reinterpret_cast<__half2*>(d_yh);
            yh2[n * 16 + tx * 2]     = __floats2half2_rn(o[0] * dv, o[1] * dv);
            yh2[n * 16 + tx * 2 + 1] = __floats2half2_rn(o[2] * dv, o[3] * dv);
        }
    }
}

// ---------------- GCN1 gather (fp16) + fused h1@gcn2_W -> xw2, y2h ----------------
__global__ void gcn1x_k(const float* __restrict__ g1b, const float* __restrict__ g2W) {
    __shared__ float Ws[HH * HH];
    for (int t = threadIdx.x; t < HH * HH; t += blockDim.x) Ws[t] = g2W[t];
    __syncthreads();
    int lane = threadIdx.x & 31;
    int n = blockIdx.x * (blockDim.x >> 5) + (threadIdx.x >> 5);
    if (n >= NN) return;
    int base = d_off[n], end = d_off[n + 1];
    float a0 = 0.f, a1 = 0.f, a2 = 0.f, a3 = 0.f;
    int k = base;
    for (; k + 4 <= end; k += 4) {
        int r0 = __ldg(&d_rows[k + 0]), r1 = __ldg(&d_rows[k + 1]);
        int r2 = __ldg(&d_rows[k + 2]), r3 = __ldg(&d_rows[k + 3]);
        a0 += __half2float(d_yh[r0 * HH + lane]);
        a1 += __half2float(d_yh[r1 * HH + lane]);
        a2 += __half2float(d_yh[r2 * HH + lane]);
        a3 += __half2float(d_yh[r3 * HH + lane]);
    }
    for (; k < end; k++) a0 += __half2float(d_yh[__ldg(&d_rows[k]) * HH + lane]);
    float acc = (a0 + a1) + (a2 + a3);
    float dv = d_dinv[n];
    float h1 = fmaxf(dv * acc + dv * dv * d_xw1[n * HH + lane] + g1b[lane], 0.f);
    float xw2 = 0.f;
    #pragma unroll
    for (int kk = 0; kk < HH; kk++)
        xw2 += __shfl_sync(0xffffffffu, h1, kk) * Ws[kk * HH + lane];
    d_xw2[n * HH + lane] = xw2;
    d_y2h[n * HH + lane] = __float2half(xw2 * dv);
}

// ---------------- GCN2 gather (fp16) + fused mean-pool accumulate ----------------
__global__ void gcn2p_k(const float* __restrict__ g2b, const int* __restrict__ batch) {
    __shared__ float red[8][HH];
    __shared__ int gs[8];
    __shared__ int uniform;
    int lane = threadIdx.x & 31, w = threadIdx.x >> 5;
    int n = blockIdx.x * 8 + w;
    float v = 0.f;
    int g = -1;
    if (n < NN) {
        g = batch[n];
        int base = d_off[n], end = d_off[n + 1];
        float a0 = 0.f, a1 = 0.f, a2 = 0.f, a3 = 0.f;
        int k = base;
        for (; k + 4 <= end; k += 4) {
            int r0 = __ldg(&d_rows[k + 0]), r1 = __ldg(&d_rows[k + 1]);
            int r2 = __ldg(&d_rows[k + 2]), r3 = __ldg(&d_rows[k + 3]);
            a0 += __half2float(d_y2h[r0 * HH + lane]);
            a1 += __half2float(d_y2h[r1 * HH + lane]);
            a2 += __half2float(d_y2h[r2 * HH + lane]);
            a3 += __half2float(d_y2h[r3 * HH + lane]);
        }
        for (; k < end; k++) a0 += __half2float(d_y2h[__ldg(&d_rows[k]) * HH + lane]);
        float acc = (a0 + a1) + (a2 + a3);
        float dv = d_dinv[n];
        v = fmaxf(dv * acc + dv * dv * d_xw2[n * HH + lane] + g2b[lane], 0.f);
    }
    red[w][lane] = v;
    if (lane == 0) gs[w] = g;
    __syncthreads();
    if (threadIdx.x == 0) {
        int gref = -1; int uni = 1;
        #pragma unroll
        for (int i = 0; i < 8; i++) {
            int gi = gs[i];
            if (gi >= 0) { if (gref < 0) gref = gi; else if (gi != gref) uni = 0; }
        }
        uniform = uni ? gref : -1;
    }
    __syncthreads();
    int u = uniform;
    if (u >= 0) {
        if (w == 0) {
            float s = red[0][lane];
            #pragma unroll
            for (int i = 1; i < 8; i++) s += red[i][lane];
            atomicAdd(&d_pooled[u * HH + lane], s);
        }
    } else {
        if (g >= 0) atomicAdd(&d_pooled[g * HH + lane], v);
    }
}

// ---------------- classifier (counts via binary search on sorted batch) ----------------
__global__ void cls_k(const int* __restrict__ batch,
                      const float* __restrict__ clsW, const float* __restrict__ clsb,
                      float* __restrict__ out) {
    int t = threadIdx.x + blockIdx.x * blockDim.x;
    if (t >= GG * CC) return;
    int g = t / CC; int j = t % CC;
    int lo = 0, hi = NN;
    while (lo < hi) { int m = (lo + hi) >> 1; if (batch[m] < g) lo = m + 1; else hi = m; }
    int s0 = lo;
    hi = NN;
    while (lo < hi) { int m = (lo + hi) >> 1; if (batch[m] < g + 1) lo = m + 1; else hi = m; }
    float cnt = fmaxf((float)(lo - s0), 1.0f);
    float inv = 1.0f / cnt;
    float s = clsb[j];
    #pragma unroll
    for (int k = 0; k < HH; k++) s += d_pooled[g * HH + k] * inv * clsW[k * CC + j];
    out[t] = s;
}

// ---------------- launch ----------------
extern "C" void kernel_launch(void* const* d_in, const int* in_sizes, int n_in,
                              void* d_out, int out_size) {
    const float* x     = (const float*)d_in[0];
    const int*   ei    = (const int*)d_in[1];
    const int*   row   = ei;
    const int*   col   = ei + EE;
    const int*   batch = (const int*)d_in[2];
    const float* fW    = (const float*)d_in[3];
    const float* fb    = (const float*)d_in[4];
    const float* W1    = (const float*)d_in[5];
    const float* b1    = (const float*)d_in[6];
    const float* W2    = (const float*)d_in[7];
    const float* b2    = (const float*)d_in[8];
    const float* g1W   = (const float*)d_in[9];
    const float* g1b   = (const float*)d_in[10];
    const float* g2W   = (const float*)d_in[11];
    const float* g2b   = (const float*)d_in[12];
    const float* clsW  = (const float*)d_in[13];
    const float* clsb  = (const float*)d_in[14];
    float* out = (float*)d_out;

    const int TB = 256;
    const int gridE    = (EE + TB - 1) / TB;
    const int gridN128 = (NN + 127) / 128;

    setup_k<<<128, TB>>>(fW, fb, W1, b1, W2, b2, g1W);
    hist_k<<<gridE, TB>>>(col);
    scanA_k<<<NBLK, 1024>>>();
    scanB_k<<<1, 32>>>();
    scanC_k<<<NBLK, 1024>>>(x);
    fill_k<<<gridE, TB>>>(row, col);
    edge_k<<<1184, TB>>>();
    gemm_k<<<gridN128, TB>>>(g1W);
    gcn1x_k<<<(NN + 7) / 8, TB>>>(g1b, g2W);
    gcn2p_k<<<(NN + 7) / 8, TB>>>(g2b, batch);
    cls_k<<<(GG * CC + TB - 1) / TB, TB>>>(batch, clsW, clsb, out);
}